// round 12
// baseline (speedup 1.0000x reference)
#include <cuda_runtime.h>
#include <cuda_bf16.h>
#include <cuda_fp16.h>
#include <math.h>
#include <stdint.h>

#define MM 100001
#define NN 50000
#define HH 256
#define KK 6
#define BB 64
#define NDEPTH 6

typedef unsigned short us;

// ---------------------------------------------------------------------------
// scratch
// ---------------------------------------------------------------------------
__device__ __align__(16) us g_xhi[(size_t)MM * HH];
__device__ __align__(16) us g_xlo[(size_t)MM * HH];
__device__ __align__(16) us g_hhi[(size_t)MM * HH];
__device__ __align__(16) us g_hlo[(size_t)MM * HH];
__device__ __align__(16) us g_shhi[(size_t)MM * HH];
__device__ __align__(16) us g_shlo[(size_t)MM * HH];
__device__ __align__(16) us g_sghi[(size_t)MM * HH];
__device__ __align__(16) us g_sglo[(size_t)MM * HH];
__device__ float  g_x3  [(size_t)MM * 3 * HH];
__device__ __align__(16) __half g_hUr [(size_t)MM * HH];
__device__ __align__(16) __half g_zlin[(size_t)MM * HH];
__device__ __align__(16) us g_Wprehi[768 * 256];
__device__ __align__(16) us g_Wprelo[768 * 256];
__device__ __align__(16) us g_Wz2hi[256 * 256];
__device__ __align__(16) us g_Wz2lo[256 * 256];
__device__ __align__(16) us g_Wh2hi[256 * 256];
__device__ __align__(16) us g_Wh2lo[256 * 256];
__device__ __align__(16) us g_Urhi[256 * 256];
__device__ __align__(16) us g_Urlo[256 * 256];

__device__ __forceinline__ float sigmf(float v) { return 1.0f / (1.0f + expf(-v)); }
__device__ __forceinline__ void split_bf(float v, us& hi, us& lo) {
    __nv_bfloat16 h = __float2bfloat16(v);
    __nv_bfloat16 l = __float2bfloat16(v - __bfloat162float(h));
    hi = *(us*)&h; lo = *(us*)&l;
}
__device__ __forceinline__ float join_bf(us hi, us lo) {
    return __bfloat162float(*(__nv_bfloat16*)&hi) + __bfloat162float(*(__nv_bfloat16*)&lo);
}
struct us2 { us x, y; };
struct us4 { us x, y, z, w; };

__device__ __forceinline__ uint32_t smem_u32(const void* p) {
    uint32_t a;
    asm("{ .reg .u64 t; cvta.to.shared.u64 t, %1; cvt.u32.u64 %0, t; }" : "=r"(a) : "l"(p));
    return a;
}
__device__ __forceinline__ void ldsm4(uint32_t* r, uint32_t addr) {
    asm volatile("ldmatrix.sync.aligned.m8n8.x4.shared.b16 {%0,%1,%2,%3}, [%4];"
        : "=r"(r[0]), "=r"(r[1]), "=r"(r[2]), "=r"(r[3]) : "r"(addr));
}
__device__ __forceinline__ void mma16816(float* d, const uint32_t* a, const uint32_t* b) {
    asm volatile("mma.sync.aligned.m16n8k16.row.col.f32.bf16.bf16.f32 "
        "{%0,%1,%2,%3}, {%4,%5,%6,%7}, {%8,%9}, {%0,%1,%2,%3};"
        : "+f"(d[0]), "+f"(d[1]), "+f"(d[2]), "+f"(d[3])
        : "r"(a[0]), "r"(a[1]), "r"(a[2]), "r"(a[3]), "r"(b[0]), "r"(b[1]));
}

// ---------------------------------------------------------------------------
// weight pack + split
// ---------------------------------------------------------------------------
__global__ void k_pack(const float* __restrict__ Wz, const float* __restrict__ Wr,
                       const float* __restrict__ Wh, const float* __restrict__ Ur) {
    int idx = blockIdx.x * blockDim.x + threadIdx.x;
    int j = idx >> 8, i = idx & 255;
    float v; us hi, lo;
    if (j < 256)       v = Wz[j * 512 + i];
    else if (j < 512)  v = Wr[(j - 256) * 256 + i];
    else if (j < 768)  v = Wh[(j - 512) * 512 + i];
    else if (j < 1024) v = Wz[(j - 768) * 512 + 256 + i];
    else if (j < 1280) v = Wh[(j - 1024) * 512 + 256 + i];
    else               v = Ur[(j - 1280) * 256 + i];
    split_bf(v, hi, lo);
    if (j < 768)        { g_Wprehi[j * 256 + i] = hi;          g_Wprelo[j * 256 + i] = lo; }
    else if (j < 1024)  { g_Wz2hi[(j - 768) * 256 + i] = hi;   g_Wz2lo[(j - 768) * 256 + i] = lo; }
    else if (j < 1280)  { g_Wh2hi[(j - 1024) * 256 + i] = hi;  g_Wh2lo[(j - 1024) * 256 + i] = lo; }
    else                { g_Urhi[(j - 1280) * 256 + i] = hi;   g_Urlo[(j - 1280) * 256 + i] = lo; }
}

// ---------------------------------------------------------------------------
// embed
// ---------------------------------------------------------------------------
__global__ void k_embed(const int* __restrict__ fnode, const int* __restrict__ fmess,
                        const float* __restrict__ emb) {
    int e = blockIdx.x * blockDim.x + threadIdx.x;
    if (e >= MM * 64) return;
    int m = e >> 6, c = (e & 63) * 4;
    int v = fnode[fmess[m]];
    float4 f = *(const float4*)(emb + (size_t)v * HH + c);
    us4 hi, lo;
    split_bf(f.x, hi.x, lo.x); split_bf(f.y, hi.y, lo.y);
    split_bf(f.z, hi.z, lo.z); split_bf(f.w, hi.w, lo.w);
    *(us4*)(g_xhi + (size_t)m * HH + c) = hi;
    *(us4*)(g_xlo + (size_t)m * HH + c) = lo;
}

// ===========================================================================
// split-bf16 mma.sync GEMM (R4 core, UNCHANGED): CTA 128x128, 8 warps,
// warp tile 32x64, k-chunk 32, 2-stage cp.async, rows stride 80B.
// ===========================================================================
#define STG 40960
#define SMEM_GEMM (2 * STG)

__device__ __forceinline__ void issue_stage(
    uint32_t sb, const us* __restrict__ Ahi, const us* __restrict__ Alo,
    const us* __restrict__ Bhi, const us* __restrict__ Blo,
    int bm, int bn, int kc)
{
    int tid = threadIdx.x;
#pragma unroll
    for (int i = 0; i < 4; i++) {           // A planes
        int v = tid + i * 256;
        int plane = v >> 9, w = v & 511;
        int rr = w >> 2, cc = w & 3;
        int row = bm + rr;
        int sz = (row < MM) ? 16 : 0;
        const us* src = (plane ? Alo : Ahi) +
            (size_t)(row < MM ? row : MM - 1) * 256 + kc + cc * 8;
        uint32_t dst = sb + plane * 10240 + rr * 80 + cc * 16;
        asm volatile("cp.async.cg.shared.global [%0], [%1], 16, %2;"
                     :: "r"(dst), "l"(src), "r"(sz));
    }
#pragma unroll
    for (int i = 0; i < 4; i++) {           // B planes
        int v = tid + i * 256;
        int plane = v >> 9, w = v & 511;
        int rr = w >> 2, cc = w & 3;
        const us* src = (plane ? Blo : Bhi) + (size_t)(bn + rr) * 256 + kc + cc * 8;
        uint32_t dst = sb + 20480 + plane * 10240 + rr * 80 + cc * 16;
        asm volatile("cp.async.cg.shared.global [%0], [%1], 16, %2;"
                     :: "r"(dst), "l"(src), "r"(16));
    }
    asm volatile("cp.async.commit_group;" ::: "memory");
}

__device__ __forceinline__ void compute_stage(uint32_t sb, int warp_m, int warp_n,
                                              int lane, float acc[2][8][4]) {
    int quad = lane >> 3, lr = lane & 7;
    int rowA = ((quad & 1) << 3) + lr;
    int colA = (quad & 2) ? 8 : 0;
    int rowB = ((quad >> 1) << 3) + lr;
    int colB = (quad & 1) ? 8 : 0;
#pragma unroll
    for (int step = 0; step < 2; step++) {
        int kb = step * 16;
        uint32_t ahi[2][4], alo[2][4], bhi[8][2], blo[8][2];
#pragma unroll
        for (int mt = 0; mt < 2; mt++) {
            uint32_t ah = sb + (warp_m * 32 + mt * 16 + rowA) * 80 + (kb + colA) * 2;
            ldsm4(ahi[mt], ah);
            ldsm4(alo[mt], ah + 10240);
        }
#pragma unroll
        for (int np = 0; np < 4; np++) {
            uint32_t bh = sb + 20480 + (warp_n * 64 + np * 16 + rowB) * 80 + (kb + colB) * 2;
            uint32_t r[4];
            ldsm4(r, bh);
            bhi[np * 2][0] = r[0]; bhi[np * 2][1] = r[1];
            bhi[np * 2 + 1][0] = r[2]; bhi[np * 2 + 1][1] = r[3];
            ldsm4(r, bh + 10240);
            blo[np * 2][0] = r[0]; blo[np * 2][1] = r[1];
            blo[np * 2 + 1][0] = r[2]; blo[np * 2 + 1][1] = r[3];
        }
#pragma unroll
        for (int mt = 0; mt < 2; mt++)
#pragma unroll
            for (int nt = 0; nt < 8; nt++) {
                mma16816(acc[mt][nt], ahi[mt], bhi[nt]);
                mma16816(acc[mt][nt], alo[mt], bhi[nt]);
                mma16816(acc[mt][nt], ahi[mt], blo[nt]);
            }
    }
}

__device__ __forceinline__ void gemm_main(
    char* smc, const us* Ahi, const us* Alo,
    const us* Whi, const us* Wlo,
    int bm, int bn, float acc[2][8][4])
{
#pragma unroll
    for (int a = 0; a < 2; a++)
#pragma unroll
        for (int b = 0; b < 8; b++)
#pragma unroll
            for (int c = 0; c < 4; c++) acc[a][b][c] = 0.0f;

    uint32_t sb = smem_u32(smc);
    int lane = threadIdx.x & 31, wid = threadIdx.x >> 5;
    int warp_m = wid & 3, warp_n = wid >> 2;

    issue_stage(sb, Ahi, Alo, Whi, Wlo, bm, bn, 0);
    for (int s = 0; s < 8; s++) {
        if (s < 7) {
            issue_stage(sb + ((s + 1) & 1) * STG, Ahi, Alo, Whi, Wlo, bm, bn, (s + 1) * 32);
            asm volatile("cp.async.wait_group 1;" ::: "memory");
        } else {
            asm volatile("cp.async.wait_group 0;" ::: "memory");
        }
        __syncthreads();
        compute_stage(sb + (s & 1) * STG, warp_m, warp_n, lane, acc);
        __syncthreads();
    }
}

// ---------------- normal GEMM (templated output type) -----------------------
template <typename OutT>
__global__ __launch_bounds__(256)
void k_gemm(const us* __restrict__ Ahi, const us* __restrict__ Alo,
            const us* __restrict__ Whi, const us* __restrict__ Wlo,
            OutT* __restrict__ C, int ldc) {
    extern __shared__ char smc[];
    int bm = blockIdx.x * 128, bn = blockIdx.y * 128;
    float acc[2][8][4];
    gemm_main(smc, Ahi, Alo, Whi, Wlo, bm, bn, acc);
    int lane = threadIdx.x & 31, wid = threadIdx.x >> 5;
    int g = lane >> 2, tig = lane & 3;
#pragma unroll
    for (int mt = 0; mt < 2; mt++) {
        int row0 = bm + (wid & 3) * 32 + mt * 16 + g;
#pragma unroll
        for (int nt = 0; nt < 8; nt++) {
            int col = bn + (wid >> 2) * 64 + nt * 8 + tig * 2;
            if (sizeof(OutT) == 2) {
                if (row0 < MM)
                    *(__half2*)((__half*)C + (size_t)row0 * ldc + col) =
                        __floats2half2_rn(acc[mt][nt][0], acc[mt][nt][1]);
                if (row0 + 8 < MM)
                    *(__half2*)((__half*)C + (size_t)(row0 + 8) * ldc + col) =
                        __floats2half2_rn(acc[mt][nt][2], acc[mt][nt][3]);
            } else {
                if (row0 < MM)
                    *(float2*)((float*)C + (size_t)row0 * ldc + col) =
                        make_float2(acc[mt][nt][0], acc[mt][nt][1]);
                if (row0 + 8 < MM)
                    *(float2*)((float*)C + (size_t)(row0 + 8) * ldc + col) =
                        make_float2(acc[mt][nt][2], acc[mt][nt][3]);
            }
        }
    }
}

// ---------------- GEMM (sumg @ Wh2^T) with fused GRU update ------------------
__device__ __forceinline__ void gru2(int row, int col, float a0, float a1,
                                     const float* __restrict__ bz,
                                     const float* __restrict__ bh,
                                     float* __restrict__ Hout) {
    if (row >= MM) return;
    size_t o768 = (size_t)row * 768 + col;
    size_t o256 = (size_t)row * 256 + col;
    float2 xz = *(const float2*)(g_x3 + o768);
    float2 xh = *(const float2*)(g_x3 + o768 + 512);
    float2 zl = __half22float2(*(const __half2*)(g_zlin + o256));
    us2 shh = *(const us2*)(g_shhi + o256);
    us2 shl = *(const us2*)(g_shlo + o256);
    float2 bzv = *(const float2*)(bz + col);
    float2 bhv = *(const float2*)(bh + col);
    float sh0 = join_bf(shh.x, shl.x);
    float sh1 = join_bf(shh.y, shl.y);
    float z0 = sigmf(xz.x + zl.x + bzv.x);
    float p0 = tanhf(xh.x + a0 + bhv.x);
    float o0 = (1.0f - z0) * sh0 + z0 * p0;
    float z1 = sigmf(xz.y + zl.y + bzv.y);
    float p1 = tanhf(xh.y + a1 + bhv.y);
    float o1 = (1.0f - z1) * sh1 + z1 * p1;
    if (row == 0) { o0 = 0.0f; o1 = 0.0f; }
    *(float2*)(Hout + o256) = make_float2(o0, o1);
    us2 hi, lo;
    split_bf(o0, hi.x, lo.x); split_bf(o1, hi.y, lo.y);
    *(us2*)(g_hhi + o256) = hi;
    *(us2*)(g_hlo + o256) = lo;
}

__global__ __launch_bounds__(256)
void k_gemm_gru(const us* __restrict__ Ahi, const us* __restrict__ Alo,
                const us* __restrict__ Whi, const us* __restrict__ Wlo,
                float* __restrict__ Hout, const float* __restrict__ bz,
                const float* __restrict__ bh) {
    extern __shared__ char smc[];
    int bm = blockIdx.x * 128, bn = blockIdx.y * 128;
    float acc[2][8][4];
    gemm_main(smc, Ahi, Alo, Whi, Wlo, bm, bn, acc);
    int lane = threadIdx.x & 31, wid = threadIdx.x >> 5;
    int g = lane >> 2, tig = lane & 3;
#pragma unroll
    for (int mt = 0; mt < 2; mt++) {
        int row0 = bm + (wid & 3) * 32 + mt * 16 + g;
#pragma unroll
        for (int nt = 0; nt < 8; nt++) {
            int col = bn + (wid >> 2) * 64 + nt * 8 + tig * 2;
            gru2(row0, col, acc[mt][nt][0], acc[mt][nt][1], bz, bh, Hout);
            gru2(row0 + 8, col, acc[mt][nt][2], acc[mt][nt][3], bz, bh, Hout);
        }
    }
}

// ---------------------------------------------------------------------------
// first GRU step (h == 0)
// ---------------------------------------------------------------------------
__global__ void k_first(float* __restrict__ h, const float* __restrict__ bz,
                        const float* __restrict__ bh) {
    int e = blockIdx.x * blockDim.x + threadIdx.x;
    if (e >= MM * 64) return;
    int m = e >> 6, c = (e & 63) * 4;
    float4 xz = *(const float4*)(g_x3 + (size_t)m * 768 + c);
    float4 xh = *(const float4*)(g_x3 + (size_t)m * 768 + 512 + c);
    float4 bzv = *(const float4*)(bz + c);
    float4 bhv = *(const float4*)(bh + c);
    float4 o;
    o.x = sigmf(xz.x + bzv.x) * tanhf(xh.x + bhv.x);
    o.y = sigmf(xz.y + bzv.y) * tanhf(xh.y + bhv.y);
    o.z = sigmf(xz.z + bzv.z) * tanhf(xh.z + bhv.z);
    o.w = sigmf(xz.w + bzv.w) * tanhf(xh.w + bhv.w);
    if (m == 0) o = make_float4(0.f, 0.f, 0.f, 0.f);
    *(float4*)(h + (size_t)m * HH + c) = o;
    us4 hi, lo;
    split_bf(o.x, hi.x, lo.x); split_bf(o.y, hi.y, lo.y);
    split_bf(o.z, hi.z, lo.z); split_bf(o.w, hi.w, lo.w);
    *(us4*)(g_hhi + (size_t)m * HH + c) = hi;
    *(us4*)(g_hlo + (size_t)m * HH + c) = lo;
}

// ---------------------------------------------------------------------------
// gather: sum_h (planes) and sum(r*h_nei) (planes); h read fp32, hUr fp16
// ---------------------------------------------------------------------------
__global__ void k_gather(const float* __restrict__ h, const int* __restrict__ mg,
                         const float* __restrict__ bu) {
    int m = blockIdx.x * blockDim.y + threadIdx.y;
    if (m >= MM) return;
    int c = threadIdx.x * 4;
    int idx[KK];
#pragma unroll
    for (int k = 0; k < KK; k++) idx[k] = mg[m * KK + k];
    float4 xr = *(const float4*)(g_x3 + (size_t)m * 768 + 256 + c);
    float4 bv = *(const float4*)(bu + c);
    float4 as = make_float4(0.f, 0.f, 0.f, 0.f);
    float4 ag = make_float4(0.f, 0.f, 0.f, 0.f);
#pragma unroll
    for (int k = 0; k < KK; k++) {
        const float4 hv = *(const float4*)(h + (size_t)idx[k] * HH + c);
        const __half2* up = (const __half2*)(g_hUr + (size_t)idx[k] * HH + c);
        float2 u0 = __half22float2(up[0]);
        float2 u1 = __half22float2(up[1]);
        float rx = sigmf(xr.x + u0.x + bv.x);
        float ry = sigmf(xr.y + u0.y + bv.y);
        float rz = sigmf(xr.z + u1.x + bv.z);
        float rw = sigmf(xr.w + u1.y + bv.w);
        as.x += hv.x; as.y += hv.y; as.z += hv.z; as.w += hv.w;
        ag.x = fmaf(rx, hv.x, ag.x); ag.y = fmaf(ry, hv.y, ag.y);
        ag.z = fmaf(rz, hv.z, ag.z); ag.w = fmaf(rw, hv.w, ag.w);
    }
    us4 hi, lo;
    split_bf(as.x, hi.x, lo.x); split_bf(as.y, hi.y, lo.y);
    split_bf(as.z, hi.z, lo.z); split_bf(as.w, hi.w, lo.w);
    *(us4*)(g_shhi + (size_t)m * HH + c) = hi;
    *(us4*)(g_shlo + (size_t)m * HH + c) = lo;
    split_bf(ag.x, hi.x, lo.x); split_bf(ag.y, hi.y, lo.y);
    split_bf(ag.z, hi.z, lo.z); split_bf(ag.w, hi.w, lo.w);
    *(us4*)(g_sghi + (size_t)m * HH + c) = hi;
    *(us4*)(g_sglo + (size_t)m * HH + c) = lo;
}

// ---------------------------------------------------------------------------
// readout (B=64 roots)
// ---------------------------------------------------------------------------
__global__ void k_readout(const int* __restrict__ scope_st, const int* __restrict__ fnode,
                          const int* __restrict__ node_graph, const float* __restrict__ emb,
                          const float* __restrict__ h, const float* __restrict__ Wo,
                          const float* __restrict__ bo, float* __restrict__ out) {
    __shared__ float fe[HH];
    __shared__ float mn[HH];
    int b = blockIdx.x, j = threadIdx.x;
    int n = scope_st[b];
    fe[j] = emb[(size_t)fnode[n] * HH + j];
    float s = 0.0f;
#pragma unroll
    for (int k = 0; k < KK; k++) s += h[(size_t)node_graph[n * KK + k] * HH + j];
    mn[j] = s;
    __syncthreads();
    float acc = bo[j];
    const float* wrow = Wo + (size_t)j * 512;
#pragma unroll 4
    for (int i = 0; i < 256; i += 4) {
        float4 w = *(const float4*)(wrow + i);
        float4 f = *(const float4*)&fe[i];
        acc = fmaf(w.x, f.x, acc); acc = fmaf(w.y, f.y, acc);
        acc = fmaf(w.z, f.z, acc); acc = fmaf(w.w, f.w, acc);
    }
#pragma unroll 4
    for (int i = 0; i < 256; i += 4) {
        float4 w = *(const float4*)(wrow + 256 + i);
        float4 f = *(const float4*)&mn[i];
        acc = fmaf(w.x, f.x, acc); acc = fmaf(w.y, f.y, acc);
        acc = fmaf(w.z, f.z, acc); acc = fmaf(w.w, f.w, acc);
    }
    out[(size_t)b * HH + j] = fmaxf(acc, 0.0f);
}

// ---------------------------------------------------------------------------
// launch
// ---------------------------------------------------------------------------
extern "C" void kernel_launch(void* const* d_in, const int* in_sizes, int n_in,
                              void* d_out, int out_size) {
    const int*   fnode      = (const int*)  d_in[0];
    const int*   fmess      = (const int*)  d_in[1];
    const int*   node_graph = (const int*)  d_in[2];
    const int*   mess_graph = (const int*)  d_in[3];
    const int*   scope_st   = (const int*)  d_in[4];
    const float* emb        = (const float*)d_in[5];
    const float* Wz         = (const float*)d_in[6];
    const float* bz         = (const float*)d_in[7];
    const float* Wr         = (const float*)d_in[8];
    const float* Ur         = (const float*)d_in[9];
    const float* bu         = (const float*)d_in[10];
    const float* Wh         = (const float*)d_in[11];
    const float* bh         = (const float*)d_in[12];
    const float* Wo         = (const float*)d_in[13];
    const float* bo         = (const float*)d_in[14];

    float* out = (float*)d_out;
    float* h = out + (size_t)BB * HH;

    cudaFuncSetAttribute(k_gemm<float>,  cudaFuncAttributeMaxDynamicSharedMemorySize, SMEM_GEMM);
    cudaFuncSetAttribute(k_gemm<__half>, cudaFuncAttributeMaxDynamicSharedMemorySize, SMEM_GEMM);
    cudaFuncSetAttribute(k_gemm_gru,     cudaFuncAttributeMaxDynamicSharedMemorySize, SMEM_GEMM);

    us *xhi, *xlo, *hhi, *hlo, *shhi, *shlo, *sghi, *sglo;
    us *Wprehi, *Wprelo, *Wz2hi, *Wz2lo, *Wh2hi, *Wh2lo, *Urhi, *Urlo;
    float *x3p; __half *hUrp, *zlinp;
    cudaGetSymbolAddress((void**)&xhi, g_xhi);   cudaGetSymbolAddress((void**)&xlo, g_xlo);
    cudaGetSymbolAddress((void**)&hhi, g_hhi);   cudaGetSymbolAddress((void**)&hlo, g_hlo);
    cudaGetSymbolAddress((void**)&shhi, g_shhi); cudaGetSymbolAddress((void**)&shlo, g_shlo);
    cudaGetSymbolAddress((void**)&sghi, g_sghi); cudaGetSymbolAddress((void**)&sglo, g_sglo);
    cudaGetSymbolAddress((void**)&Wprehi, g_Wprehi); cudaGetSymbolAddress((void**)&Wprelo, g_Wprelo);
    cudaGetSymbolAddress((void**)&Wz2hi, g_Wz2hi);   cudaGetSymbolAddress((void**)&Wz2lo, g_Wz2lo);
    cudaGetSymbolAddress((void**)&Wh2hi, g_Wh2hi);   cudaGetSymbolAddress((void**)&Wh2lo, g_Wh2lo);
    cudaGetSymbolAddress((void**)&Urhi, g_Urhi);     cudaGetSymbolAddress((void**)&Urlo, g_Urlo);
    cudaGetSymbolAddress((void**)&x3p, g_x3);
    cudaGetSymbolAddress((void**)&zlinp, g_zlin);
    cudaGetSymbolAddress((void**)&hUrp, g_hUr);

    const int ETH = 256;
    const int EBL = (MM * 64 + ETH - 1) / ETH;
    const int MT  = (MM + 127) / 128;

    k_pack <<<1536, 256>>>(Wz, Wr, Wh, Ur);
    k_embed<<<EBL, ETH>>>(fnode, fmess, emb);

    k_gemm<float><<<dim3(MT, 6), 256, SMEM_GEMM>>>(xhi, xlo, Wprehi, Wprelo, x3p, 768);
    k_first<<<EBL, ETH>>>(h, bz, bh);

    for (int it = 1; it < NDEPTH; it++) {
        k_gemm<__half><<<dim3(MT, 2), 256, SMEM_GEMM>>>(hhi, hlo, Urhi, Urlo, hUrp, 256);
        k_gather<<<(MM + 3) / 4, dim3(64, 4)>>>(h, mess_graph, bu);
        k_gemm<__half><<<dim3(MT, 2), 256, SMEM_GEMM>>>(shhi, shlo, Wz2hi, Wz2lo, zlinp, 256);
        k_gemm_gru<<<dim3(MT, 2), 256, SMEM_GEMM>>>(sghi, sglo, Wh2hi, Wh2lo, h, bz, bh);
    }

    k_readout<<<BB, HH>>>(scope_st, fnode, node_graph, emb, h, Wo, bo, out);
}

// round 13
// speedup vs baseline: 1.4757x; 1.4757x over previous
#include <cuda_runtime.h>
#include <cuda_bf16.h>
#include <cuda_fp16.h>
#include <math.h>
#include <stdint.h>

#define MM 100001
#define NN 50000
#define HH 256
#define KK 6
#define BB 64
#define NDEPTH 6

typedef unsigned short us;

// ---------------------------------------------------------------------------
// scratch
// ---------------------------------------------------------------------------
__device__ __align__(16) us g_xhi[(size_t)MM * HH];
__device__ __align__(16) us g_xlo[(size_t)MM * HH];
__device__ __align__(16) us g_hhi[(size_t)MM * HH];
__device__ __align__(16) us g_hlo[(size_t)MM * HH];
__device__ __align__(16) us g_shhi[(size_t)MM * HH];
__device__ __align__(16) us g_shlo[(size_t)MM * HH];
__device__ __align__(16) us g_sghi[(size_t)MM * HH];
__device__ __align__(16) us g_sglo[(size_t)MM * HH];
__device__ float  g_x3  [(size_t)MM * 3 * HH];
__device__ __align__(16) __half g_hUr [(size_t)MM * HH];
__device__ __align__(16) __half g_zlin[(size_t)MM * HH];
__device__ __align__(16) us g_Wprehi[768 * 256];
__device__ __align__(16) us g_Wprelo[768 * 256];
__device__ __align__(16) us g_Wz2hi[256 * 256];
__device__ __align__(16) us g_Wz2lo[256 * 256];
__device__ __align__(16) us g_Wh2hi[256 * 256];
__device__ __align__(16) us g_Wh2lo[256 * 256];
__device__ __align__(16) us g_Urhi[256 * 256];
__device__ __align__(16) us g_Urlo[256 * 256];

__device__ __forceinline__ float sigmf(float v) { return 1.0f / (1.0f + expf(-v)); }
__device__ __forceinline__ void split_bf(float v, us& hi, us& lo) {
    __nv_bfloat16 h = __float2bfloat16(v);
    __nv_bfloat16 l = __float2bfloat16(v - __bfloat162float(h));
    hi = *(us*)&h; lo = *(us*)&l;
}
__device__ __forceinline__ float join_bf(us hi, us lo) {
    return __bfloat162float(*(__nv_bfloat16*)&hi) + __bfloat162float(*(__nv_bfloat16*)&lo);
}
struct us2 { us x, y; };
struct us4 { us x, y, z, w; };

__device__ __forceinline__ uint32_t smem_u32(const void* p) {
    uint32_t a;
    asm("{ .reg .u64 t; cvta.to.shared.u64 t, %1; cvt.u32.u64 %0, t; }" : "=r"(a) : "l"(p));
    return a;
}
__device__ __forceinline__ void ldsm4(uint32_t* r, uint32_t addr) {
    asm volatile("ldmatrix.sync.aligned.m8n8.x4.shared.b16 {%0,%1,%2,%3}, [%4];"
        : "=r"(r[0]), "=r"(r[1]), "=r"(r[2]), "=r"(r[3]) : "r"(addr));
}
__device__ __forceinline__ void mma16816(float* d, const uint32_t* a, const uint32_t* b) {
    asm volatile("mma.sync.aligned.m16n8k16.row.col.f32.bf16.bf16.f32 "
        "{%0,%1,%2,%3}, {%4,%5,%6,%7}, {%8,%9}, {%0,%1,%2,%3};"
        : "+f"(d[0]), "+f"(d[1]), "+f"(d[2]), "+f"(d[3])
        : "r"(a[0]), "r"(a[1]), "r"(a[2]), "r"(a[3]), "r"(b[0]), "r"(b[1]));
}

// ---------------------------------------------------------------------------
// weight pack + split
// ---------------------------------------------------------------------------
__global__ void k_pack(const float* __restrict__ Wz, const float* __restrict__ Wr,
                       const float* __restrict__ Wh, const float* __restrict__ Ur) {
    int idx = blockIdx.x * blockDim.x + threadIdx.x;
    int j = idx >> 8, i = idx & 255;
    float v; us hi, lo;
    if (j < 256)       v = Wz[j * 512 + i];
    else if (j < 512)  v = Wr[(j - 256) * 256 + i];
    else if (j < 768)  v = Wh[(j - 512) * 512 + i];
    else if (j < 1024) v = Wz[(j - 768) * 512 + 256 + i];
    else if (j < 1280) v = Wh[(j - 1024) * 512 + 256 + i];
    else               v = Ur[(j - 1280) * 256 + i];
    split_bf(v, hi, lo);
    if (j < 768)        { g_Wprehi[j * 256 + i] = hi;          g_Wprelo[j * 256 + i] = lo; }
    else if (j < 1024)  { g_Wz2hi[(j - 768) * 256 + i] = hi;   g_Wz2lo[(j - 768) * 256 + i] = lo; }
    else if (j < 1280)  { g_Wh2hi[(j - 1024) * 256 + i] = hi;  g_Wh2lo[(j - 1024) * 256 + i] = lo; }
    else                { g_Urhi[(j - 1280) * 256 + i] = hi;   g_Urlo[(j - 1280) * 256 + i] = lo; }
}

// ---------------------------------------------------------------------------
// embed
// ---------------------------------------------------------------------------
__global__ void k_embed(const int* __restrict__ fnode, const int* __restrict__ fmess,
                        const float* __restrict__ emb) {
    int e = blockIdx.x * blockDim.x + threadIdx.x;
    if (e >= MM * 64) return;
    int m = e >> 6, c = (e & 63) * 4;
    int v = fnode[fmess[m]];
    float4 f = *(const float4*)(emb + (size_t)v * HH + c);
    us4 hi, lo;
    split_bf(f.x, hi.x, lo.x); split_bf(f.y, hi.y, lo.y);
    split_bf(f.z, hi.z, lo.z); split_bf(f.w, hi.w, lo.w);
    *(us4*)(g_xhi + (size_t)m * HH + c) = hi;
    *(us4*)(g_xlo + (size_t)m * HH + c) = lo;
}

// ===========================================================================
// split-bf16 mma.sync GEMM (R4 core, UNCHANGED): CTA 128x128, 8 warps,
// warp tile 32x64, k-chunk 32, 2-stage cp.async, rows stride 80B.
// ===========================================================================
#define STG 40960
#define SMEM_GEMM (2 * STG)

__device__ __forceinline__ void issue_stage(
    uint32_t sb, const us* __restrict__ Ahi, const us* __restrict__ Alo,
    const us* __restrict__ Bhi, const us* __restrict__ Blo,
    int bm, int bn, int kc)
{
    int tid = threadIdx.x;
#pragma unroll
    for (int i = 0; i < 4; i++) {           // A planes
        int v = tid + i * 256;
        int plane = v >> 9, w = v & 511;
        int rr = w >> 2, cc = w & 3;
        int row = bm + rr;
        int sz = (row < MM) ? 16 : 0;
        const us* src = (plane ? Alo : Ahi) +
            (size_t)(row < MM ? row : MM - 1) * 256 + kc + cc * 8;
        uint32_t dst = sb + plane * 10240 + rr * 80 + cc * 16;
        asm volatile("cp.async.cg.shared.global [%0], [%1], 16, %2;"
                     :: "r"(dst), "l"(src), "r"(sz));
    }
#pragma unroll
    for (int i = 0; i < 4; i++) {           // B planes
        int v = tid + i * 256;
        int plane = v >> 9, w = v & 511;
        int rr = w >> 2, cc = w & 3;
        const us* src = (plane ? Blo : Bhi) + (size_t)(bn + rr) * 256 + kc + cc * 8;
        uint32_t dst = sb + 20480 + plane * 10240 + rr * 80 + cc * 16;
        asm volatile("cp.async.cg.shared.global [%0], [%1], 16, %2;"
                     :: "r"(dst), "l"(src), "r"(16));
    }
    asm volatile("cp.async.commit_group;" ::: "memory");
}

__device__ __forceinline__ void compute_stage(uint32_t sb, int warp_m, int warp_n,
                                              int lane, float acc[2][8][4]) {
    int quad = lane >> 3, lr = lane & 7;
    int rowA = ((quad & 1) << 3) + lr;
    int colA = (quad & 2) ? 8 : 0;
    int rowB = ((quad >> 1) << 3) + lr;
    int colB = (quad & 1) ? 8 : 0;
#pragma unroll
    for (int step = 0; step < 2; step++) {
        int kb = step * 16;
        uint32_t ahi[2][4], alo[2][4], bhi[8][2], blo[8][2];
#pragma unroll
        for (int mt = 0; mt < 2; mt++) {
            uint32_t ah = sb + (warp_m * 32 + mt * 16 + rowA) * 80 + (kb + colA) * 2;
            ldsm4(ahi[mt], ah);
            ldsm4(alo[mt], ah + 10240);
        }
#pragma unroll
        for (int np = 0; np < 4; np++) {
            uint32_t bh = sb + 20480 + (warp_n * 64 + np * 16 + rowB) * 80 + (kb + colB) * 2;
            uint32_t r[4];
            ldsm4(r, bh);
            bhi[np * 2][0] = r[0]; bhi[np * 2][1] = r[1];
            bhi[np * 2 + 1][0] = r[2]; bhi[np * 2 + 1][1] = r[3];
            ldsm4(r, bh + 10240);
            blo[np * 2][0] = r[0]; blo[np * 2][1] = r[1];
            blo[np * 2 + 1][0] = r[2]; blo[np * 2 + 1][1] = r[3];
        }
#pragma unroll
        for (int mt = 0; mt < 2; mt++)
#pragma unroll
            for (int nt = 0; nt < 8; nt++) {
                mma16816(acc[mt][nt], ahi[mt], bhi[nt]);
                mma16816(acc[mt][nt], alo[mt], bhi[nt]);
                mma16816(acc[mt][nt], ahi[mt], blo[nt]);
            }
    }
}

__device__ __forceinline__ void gemm_main(
    char* smc, const us* Ahi, const us* Alo,
    const us* Whi, const us* Wlo,
    int bm, int bn, float acc[2][8][4])
{
#pragma unroll
    for (int a = 0; a < 2; a++)
#pragma unroll
        for (int b = 0; b < 8; b++)
#pragma unroll
            for (int c = 0; c < 4; c++) acc[a][b][c] = 0.0f;

    uint32_t sb = smem_u32(smc);
    int lane = threadIdx.x & 31, wid = threadIdx.x >> 5;
    int warp_m = wid & 3, warp_n = wid >> 2;

    issue_stage(sb, Ahi, Alo, Whi, Wlo, bm, bn, 0);
    for (int s = 0; s < 8; s++) {
        if (s < 7) {
            issue_stage(sb + ((s + 1) & 1) * STG, Ahi, Alo, Whi, Wlo, bm, bn, (s + 1) * 32);
            asm volatile("cp.async.wait_group 1;" ::: "memory");
        } else {
            asm volatile("cp.async.wait_group 0;" ::: "memory");
        }
        __syncthreads();
        compute_stage(sb + (s & 1) * STG, warp_m, warp_n, lane, acc);
        __syncthreads();
    }
}

// ---------------- normal GEMM (templated output type) -----------------------
template <typename OutT>
__global__ __launch_bounds__(256)
void k_gemm(const us* __restrict__ Ahi, const us* __restrict__ Alo,
            const us* __restrict__ Whi, const us* __restrict__ Wlo,
            OutT* __restrict__ C, int ldc) {
    extern __shared__ char smc[];
    int bm = blockIdx.x * 128, bn = blockIdx.y * 128;
    float acc[2][8][4];
    gemm_main(smc, Ahi, Alo, Whi, Wlo, bm, bn, acc);
    int lane = threadIdx.x & 31, wid = threadIdx.x >> 5;
    int g = lane >> 2, tig = lane & 3;
#pragma unroll
    for (int mt = 0; mt < 2; mt++) {
        int row0 = bm + (wid & 3) * 32 + mt * 16 + g;
#pragma unroll
        for (int nt = 0; nt < 8; nt++) {
            int col = bn + (wid >> 2) * 64 + nt * 8 + tig * 2;
            if (sizeof(OutT) == 2) {
                if (row0 < MM)
                    *(__half2*)((__half*)C + (size_t)row0 * ldc + col) =
                        __floats2half2_rn(acc[mt][nt][0], acc[mt][nt][1]);
                if (row0 + 8 < MM)
                    *(__half2*)((__half*)C + (size_t)(row0 + 8) * ldc + col) =
                        __floats2half2_rn(acc[mt][nt][2], acc[mt][nt][3]);
            } else {
                if (row0 < MM)
                    *(float2*)((float*)C + (size_t)row0 * ldc + col) =
                        make_float2(acc[mt][nt][0], acc[mt][nt][1]);
                if (row0 + 8 < MM)
                    *(float2*)((float*)C + (size_t)(row0 + 8) * ldc + col) =
                        make_float2(acc[mt][nt][2], acc[mt][nt][3]);
            }
        }
    }
}

// ---------------- GEMM (sumg @ Wh2^T) with fused GRU update ------------------
__device__ __forceinline__ void gru2(int row, int col, float a0, float a1,
                                     const float* __restrict__ bz,
                                     const float* __restrict__ bh,
                                     float* __restrict__ Hout) {
    if (row >= MM) return;
    size_t o768 = (size_t)row * 768 + col;
    size_t o256 = (size_t)row * 256 + col;
    float2 xz = *(const float2*)(g_x3 + o768);
    float2 xh = *(const float2*)(g_x3 + o768 + 512);
    float2 zl = __half22float2(*(const __half2*)(g_zlin + o256));
    us2 shh = *(const us2*)(g_shhi + o256);
    us2 shl = *(const us2*)(g_shlo + o256);
    float2 bzv = *(const float2*)(bz + col);
    float2 bhv = *(const float2*)(bh + col);
    float sh0 = join_bf(shh.x, shl.x);
    float sh1 = join_bf(shh.y, shl.y);
    float z0 = sigmf(xz.x + zl.x + bzv.x);
    float p0 = tanhf(xh.x + a0 + bhv.x);
    float o0 = (1.0f - z0) * sh0 + z0 * p0;
    float z1 = sigmf(xz.y + zl.y + bzv.y);
    float p1 = tanhf(xh.y + a1 + bhv.y);
    float o1 = (1.0f - z1) * sh1 + z1 * p1;
    if (row == 0) { o0 = 0.0f; o1 = 0.0f; }
    *(float2*)(Hout + o256) = make_float2(o0, o1);
    us2 hi, lo;
    split_bf(o0, hi.x, lo.x); split_bf(o1, hi.y, lo.y);
    *(us2*)(g_hhi + o256) = hi;
    *(us2*)(g_hlo + o256) = lo;
}

__global__ __launch_bounds__(256)
void k_gemm_gru(const us* __restrict__ Ahi, const us* __restrict__ Alo,
                const us* __restrict__ Whi, const us* __restrict__ Wlo,
                float* __restrict__ Hout, const float* __restrict__ bz,
                const float* __restrict__ bh) {
    extern __shared__ char smc[];
    int bm = blockIdx.x * 128, bn = blockIdx.y * 128;
    float acc[2][8][4];
    gemm_main(smc, Ahi, Alo, Whi, Wlo, bm, bn, acc);
    int lane = threadIdx.x & 31, wid = threadIdx.x >> 5;
    int g = lane >> 2, tig = lane & 3;
#pragma unroll
    for (int mt = 0; mt < 2; mt++) {
        int row0 = bm + (wid & 3) * 32 + mt * 16 + g;
#pragma unroll
        for (int nt = 0; nt < 8; nt++) {
            int col = bn + (wid >> 2) * 64 + nt * 8 + tig * 2;
            gru2(row0, col, acc[mt][nt][0], acc[mt][nt][1], bz, bh, Hout);
            gru2(row0 + 8, col, acc[mt][nt][2], acc[mt][nt][3], bz, bh, Hout);
        }
    }
}

// ---------------------------------------------------------------------------
// first GRU step (h == 0)
// ---------------------------------------------------------------------------
__global__ void k_first(float* __restrict__ h, const float* __restrict__ bz,
                        const float* __restrict__ bh) {
    int e = blockIdx.x * blockDim.x + threadIdx.x;
    if (e >= MM * 64) return;
    int m = e >> 6, c = (e & 63) * 4;
    float4 xz = *(const float4*)(g_x3 + (size_t)m * 768 + c);
    float4 xh = *(const float4*)(g_x3 + (size_t)m * 768 + 512 + c);
    float4 bzv = *(const float4*)(bz + c);
    float4 bhv = *(const float4*)(bh + c);
    float4 o;
    o.x = sigmf(xz.x + bzv.x) * tanhf(xh.x + bhv.x);
    o.y = sigmf(xz.y + bzv.y) * tanhf(xh.y + bhv.y);
    o.z = sigmf(xz.z + bzv.z) * tanhf(xh.z + bhv.z);
    o.w = sigmf(xz.w + bzv.w) * tanhf(xh.w + bhv.w);
    if (m == 0) o = make_float4(0.f, 0.f, 0.f, 0.f);
    *(float4*)(h + (size_t)m * HH + c) = o;
    us4 hi, lo;
    split_bf(o.x, hi.x, lo.x); split_bf(o.y, hi.y, lo.y);
    split_bf(o.z, hi.z, lo.z); split_bf(o.w, hi.w, lo.w);
    *(us4*)(g_hhi + (size_t)m * HH + c) = hi;
    *(us4*)(g_hlo + (size_t)m * HH + c) = lo;
}

// ---------------------------------------------------------------------------
// gather: sum_h (planes) and sum(r*h_nei) (planes); h read fp32, hUr fp16
// ---------------------------------------------------------------------------
__global__ void k_gather(const float* __restrict__ h, const int* __restrict__ mg,
                         const float* __restrict__ bu) {
    int m = blockIdx.x * blockDim.y + threadIdx.y;
    if (m >= MM) return;
    int c = threadIdx.x * 4;
    int idx[KK];
#pragma unroll
    for (int k = 0; k < KK; k++) idx[k] = mg[m * KK + k];
    float4 xr = *(const float4*)(g_x3 + (size_t)m * 768 + 256 + c);
    float4 bv = *(const float4*)(bu + c);
    float4 as = make_float4(0.f, 0.f, 0.f, 0.f);
    float4 ag = make_float4(0.f, 0.f, 0.f, 0.f);
#pragma unroll
    for (int k = 0; k < KK; k++) {
        const float4 hv = *(const float4*)(h + (size_t)idx[k] * HH + c);
        const __half2* up = (const __half2*)(g_hUr + (size_t)idx[k] * HH + c);
        float2 u0 = __half22float2(up[0]);
        float2 u1 = __half22float2(up[1]);
        float rx = sigmf(xr.x + u0.x + bv.x);
        float ry = sigmf(xr.y + u0.y + bv.y);
        float rz = sigmf(xr.z + u1.x + bv.z);
        float rw = sigmf(xr.w + u1.y + bv.w);
        as.x += hv.x; as.y += hv.y; as.z += hv.z; as.w += hv.w;
        ag.x = fmaf(rx, hv.x, ag.x); ag.y = fmaf(ry, hv.y, ag.y);
        ag.z = fmaf(rz, hv.z, ag.z); ag.w = fmaf(rw, hv.w, ag.w);
    }
    us4 hi, lo;
    split_bf(as.x, hi.x, lo.x); split_bf(as.y, hi.y, lo.y);
    split_bf(as.z, hi.z, lo.z); split_bf(as.w, hi.w, lo.w);
    *(us4*)(g_shhi + (size_t)m * HH + c) = hi;
    *(us4*)(g_shlo + (size_t)m * HH + c) = lo;
    split_bf(ag.x, hi.x, lo.x); split_bf(ag.y, hi.y, lo.y);
    split_bf(ag.z, hi.z, lo.z); split_bf(ag.w, hi.w, lo.w);
    *(us4*)(g_sghi + (size_t)m * HH + c) = hi;
    *(us4*)(g_sglo + (size_t)m * HH + c) = lo;
}

// ---------------------------------------------------------------------------
// readout (B=64 roots)
// ---------------------------------------------------------------------------
__global__ void k_readout(const int* __restrict__ scope_st, const int* __restrict__ fnode,
                          const int* __restrict__ node_graph, const float* __restrict__ emb,
                          const float* __restrict__ h, const float* __restrict__ Wo,
                          const float* __restrict__ bo, float* __restrict__ out) {
    __shared__ float fe[HH];
    __shared__ float mn[HH];
    int b = blockIdx.x, j = threadIdx.x;
    int n = scope_st[b];
    fe[j] = emb[(size_t)fnode[n] * HH + j];
    float s = 0.0f;
#pragma unroll
    for (int k = 0; k < KK; k++) s += h[(size_t)node_graph[n * KK + k] * HH + j];
    mn[j] = s;
    __syncthreads();
    float acc = bo[j];
    const float* wrow = Wo + (size_t)j * 512;
#pragma unroll 4
    for (int i = 0; i < 256; i += 4) {
        float4 w = *(const float4*)(wrow + i);
        float4 f = *(const float4*)&fe[i];
        acc = fmaf(w.x, f.x, acc); acc = fmaf(w.y, f.y, acc);
        acc = fmaf(w.z, f.z, acc); acc = fmaf(w.w, f.w, acc);
    }
#pragma unroll 4
    for (int i = 0; i < 256; i += 4) {
        float4 w = *(const float4*)(wrow + 256 + i);
        float4 f = *(const float4*)&mn[i];
        acc = fmaf(w.x, f.x, acc); acc = fmaf(w.y, f.y, acc);
        acc = fmaf(w.z, f.z, acc); acc = fmaf(w.w, f.w, acc);
    }
    out[(size_t)b * HH + j] = fmaxf(acc, 0.0f);
}

// ---------------------------------------------------------------------------
// launch
// ---------------------------------------------------------------------------
extern "C" void kernel_launch(void* const* d_in, const int* in_sizes, int n_in,
                              void* d_out, int out_size) {
    const int*   fnode      = (const int*)  d_in[0];
    const int*   fmess      = (const int*)  d_in[1];
    const int*   node_graph = (const int*)  d_in[2];
    const int*   mess_graph = (const int*)  d_in[3];
    const int*   scope_st   = (const int*)  d_in[4];
    const float* emb        = (const float*)d_in[5];
    const float* Wz         = (const float*)d_in[6];
    const float* bz         = (const float*)d_in[7];
    const float* Wr         = (const float*)d_in[8];
    const float* Ur         = (const float*)d_in[9];
    const float* bu         = (const float*)d_in[10];
    const float* Wh         = (const float*)d_in[11];
    const float* bh         = (const float*)d_in[12];
    const float* Wo         = (const float*)d_in[13];
    const float* bo         = (const float*)d_in[14];

    float* out = (float*)d_out;
    float* h = out + (size_t)BB * HH;

    cudaFuncSetAttribute(k_gemm<float>,  cudaFuncAttributeMaxDynamicSharedMemorySize, SMEM_GEMM);
    cudaFuncSetAttribute(k_gemm<__half>, cudaFuncAttributeMaxDynamicSharedMemorySize, SMEM_GEMM);
    cudaFuncSetAttribute(k_gemm_gru,     cudaFuncAttributeMaxDynamicSharedMemorySize, SMEM_GEMM);

    us *xhi, *xlo, *hhi, *hlo, *shhi, *shlo, *sghi, *sglo;
    us *Wprehi, *Wprelo, *Wz2hi, *Wz2lo, *Wh2hi, *Wh2lo, *Urhi, *Urlo;
    float *x3p; __half *hUrp, *zlinp;
    cudaGetSymbolAddress((void**)&xhi, g_xhi);   cudaGetSymbolAddress((void**)&xlo, g_xlo);
    cudaGetSymbolAddress((void**)&hhi, g_hhi);   cudaGetSymbolAddress((void**)&hlo, g_hlo);
    cudaGetSymbolAddress((void**)&shhi, g_shhi); cudaGetSymbolAddress((void**)&shlo, g_shlo);
    cudaGetSymbolAddress((void**)&sghi, g_sghi); cudaGetSymbolAddress((void**)&sglo, g_sglo);
    cudaGetSymbolAddress((void**)&Wprehi, g_Wprehi); cudaGetSymbolAddress((void**)&Wprelo, g_Wprelo);
    cudaGetSymbolAddress((void**)&Wz2hi, g_Wz2hi);   cudaGetSymbolAddress((void**)&Wz2lo, g_Wz2lo);
    cudaGetSymbolAddress((void**)&Wh2hi, g_Wh2hi);   cudaGetSymbolAddress((void**)&Wh2lo, g_Wh2lo);
    cudaGetSymbolAddress((void**)&Urhi, g_Urhi);     cudaGetSymbolAddress((void**)&Urlo, g_Urlo);
    cudaGetSymbolAddress((void**)&x3p, g_x3);
    cudaGetSymbolAddress((void**)&zlinp, g_zlin);
    cudaGetSymbolAddress((void**)&hUrp, g_hUr);

    const int ETH = 256;
    const int EBL = (MM * 64 + ETH - 1) / ETH;
    const int MT  = (MM + 127) / 128;

    k_pack <<<1536, 256>>>(Wz, Wr, Wh, Ur);
    k_embed<<<EBL, ETH>>>(fnode, fmess, emb);

    k_gemm<float><<<dim3(MT, 6), 256, SMEM_GEMM>>>(xhi, xlo, Wprehi, Wprelo, x3p, 768);
    k_first<<<EBL, ETH>>>(h, bz, bh);

    for (int it = 1; it < NDEPTH; it++) {
        k_gemm<__half><<<dim3(MT, 2), 256, SMEM_GEMM>>>(hhi, hlo, Urhi, Urlo, hUrp, 256);
        k_gather<<<(MM + 3) / 4, dim3(64, 4)>>>(h, mess_graph, bu);
        k_gemm<__half><<<dim3(MT, 2), 256, SMEM_GEMM>>>(shhi, shlo, Wz2hi, Wz2lo, zlinp, 256);
        k_gemm_gru<<<dim3(MT, 2), 256, SMEM_GEMM>>>(sghi, sglo, Wh2hi, Wh2lo, h, bz, bh);
    }

    k_readout<<<BB, HH>>>(scope_st, fnode, node_graph, emb, h, Wo, bo, out);
}

// round 14
// speedup vs baseline: 1.4924x; 1.0113x over previous
#include <cuda_runtime.h>
#include <cuda_bf16.h>
#include <cuda_fp16.h>
#include <math.h>
#include <stdint.h>

#define MM 100001
#define NN 50000
#define HH 256
#define KK 6
#define BB 64
#define NDEPTH 6

typedef unsigned short us;

// ---------------------------------------------------------------------------
// scratch
// ---------------------------------------------------------------------------
__device__ __align__(16) us g_xhi[(size_t)MM * HH];
__device__ __align__(16) us g_xlo[(size_t)MM * HH];
__device__ __align__(16) us g_hhi[(size_t)MM * HH];
__device__ __align__(16) us g_hlo[(size_t)MM * HH];
__device__ __align__(16) us g_shhi[(size_t)MM * HH];
__device__ __align__(16) us g_shlo[(size_t)MM * HH];
__device__ __align__(16) us g_sghi[(size_t)MM * HH];
__device__ __align__(16) us g_sglo[(size_t)MM * HH];
__device__ __align__(16) __half g_x3 [(size_t)MM * 3 * HH];   // fp16 now
__device__ __align__(16) __half g_hUr [(size_t)MM * HH];
__device__ __align__(16) __half g_zlin[(size_t)MM * HH];
__device__ __align__(16) us g_Wprehi[768 * 256];
__device__ __align__(16) us g_Wprelo[768 * 256];
__device__ __align__(16) us g_Wz2hi[256 * 256];
__device__ __align__(16) us g_Wz2lo[256 * 256];
__device__ __align__(16) us g_Wh2hi[256 * 256];
__device__ __align__(16) us g_Wh2lo[256 * 256];
__device__ __align__(16) us g_Urhi[256 * 256];
__device__ __align__(16) us g_Urlo[256 * 256];

__device__ __forceinline__ float sigmf(float v) { return 1.0f / (1.0f + expf(-v)); }
__device__ __forceinline__ void split_bf(float v, us& hi, us& lo) {
    __nv_bfloat16 h = __float2bfloat16(v);
    __nv_bfloat16 l = __float2bfloat16(v - __bfloat162float(h));
    hi = *(us*)&h; lo = *(us*)&l;
}
__device__ __forceinline__ float join_bf(us hi, us lo) {
    return __bfloat162float(*(__nv_bfloat16*)&hi) + __bfloat162float(*(__nv_bfloat16*)&lo);
}
struct us2 { us x, y; };
struct us4 { us x, y, z, w; };

__device__ __forceinline__ uint32_t smem_u32(const void* p) {
    uint32_t a;
    asm("{ .reg .u64 t; cvta.to.shared.u64 t, %1; cvt.u32.u64 %0, t; }" : "=r"(a) : "l"(p));
    return a;
}
__device__ __forceinline__ void ldsm4(uint32_t* r, uint32_t addr) {
    asm volatile("ldmatrix.sync.aligned.m8n8.x4.shared.b16 {%0,%1,%2,%3}, [%4];"
        : "=r"(r[0]), "=r"(r[1]), "=r"(r[2]), "=r"(r[3]) : "r"(addr));
}
__device__ __forceinline__ void mma16816(float* d, const uint32_t* a, const uint32_t* b) {
    asm volatile("mma.sync.aligned.m16n8k16.row.col.f32.bf16.bf16.f32 "
        "{%0,%1,%2,%3}, {%4,%5,%6,%7}, {%8,%9}, {%0,%1,%2,%3};"
        : "+f"(d[0]), "+f"(d[1]), "+f"(d[2]), "+f"(d[3])
        : "r"(a[0]), "r"(a[1]), "r"(a[2]), "r"(a[3]), "r"(b[0]), "r"(b[1]));
}

// ---------------------------------------------------------------------------
// weight pack + split
// ---------------------------------------------------------------------------
__global__ void k_pack(const float* __restrict__ Wz, const float* __restrict__ Wr,
                       const float* __restrict__ Wh, const float* __restrict__ Ur) {
    int idx = blockIdx.x * blockDim.x + threadIdx.x;
    int j = idx >> 8, i = idx & 255;
    float v; us hi, lo;
    if (j < 256)       v = Wz[j * 512 + i];
    else if (j < 512)  v = Wr[(j - 256) * 256 + i];
    else if (j < 768)  v = Wh[(j - 512) * 512 + i];
    else if (j < 1024) v = Wz[(j - 768) * 512 + 256 + i];
    else if (j < 1280) v = Wh[(j - 1024) * 512 + 256 + i];
    else               v = Ur[(j - 1280) * 256 + i];
    split_bf(v, hi, lo);
    if (j < 768)        { g_Wprehi[j * 256 + i] = hi;          g_Wprelo[j * 256 + i] = lo; }
    else if (j < 1024)  { g_Wz2hi[(j - 768) * 256 + i] = hi;   g_Wz2lo[(j - 768) * 256 + i] = lo; }
    else if (j < 1280)  { g_Wh2hi[(j - 1024) * 256 + i] = hi;  g_Wh2lo[(j - 1024) * 256 + i] = lo; }
    else                { g_Urhi[(j - 1280) * 256 + i] = hi;   g_Urlo[(j - 1280) * 256 + i] = lo; }
}

// ---------------------------------------------------------------------------
// embed
// ---------------------------------------------------------------------------
__global__ void k_embed(const int* __restrict__ fnode, const int* __restrict__ fmess,
                        const float* __restrict__ emb) {
    int e = blockIdx.x * blockDim.x + threadIdx.x;
    if (e >= MM * 64) return;
    int m = e >> 6, c = (e & 63) * 4;
    int v = fnode[fmess[m]];
    float4 f = *(const float4*)(emb + (size_t)v * HH + c);
    us4 hi, lo;
    split_bf(f.x, hi.x, lo.x); split_bf(f.y, hi.y, lo.y);
    split_bf(f.z, hi.z, lo.z); split_bf(f.w, hi.w, lo.w);
    *(us4*)(g_xhi + (size_t)m * HH + c) = hi;
    *(us4*)(g_xlo + (size_t)m * HH + c) = lo;
}

// ===========================================================================
// split-bf16 mma.sync GEMM (R4 core, UNCHANGED): CTA 128x128, 8 warps,
// warp tile 32x64, k-chunk 32, 2-stage cp.async, rows stride 80B.
// ===========================================================================
#define STG 40960
#define SMEM_GEMM (2 * STG)

__device__ __forceinline__ void issue_stage(
    uint32_t sb, const us* __restrict__ Ahi, const us* __restrict__ Alo,
    const us* __restrict__ Bhi, const us* __restrict__ Blo,
    int bm, int bn, int kc)
{
    int tid = threadIdx.x;
#pragma unroll
    for (int i = 0; i < 4; i++) {           // A planes
        int v = tid + i * 256;
        int plane = v >> 9, w = v & 511;
        int rr = w >> 2, cc = w & 3;
        int row = bm + rr;
        int sz = (row < MM) ? 16 : 0;
        const us* src = (plane ? Alo : Ahi) +
            (size_t)(row < MM ? row : MM - 1) * 256 + kc + cc * 8;
        uint32_t dst = sb + plane * 10240 + rr * 80 + cc * 16;
        asm volatile("cp.async.cg.shared.global [%0], [%1], 16, %2;"
                     :: "r"(dst), "l"(src), "r"(sz));
    }
#pragma unroll
    for (int i = 0; i < 4; i++) {           // B planes
        int v = tid + i * 256;
        int plane = v >> 9, w = v & 511;
        int rr = w >> 2, cc = w & 3;
        const us* src = (plane ? Blo : Bhi) + (size_t)(bn + rr) * 256 + kc + cc * 8;
        uint32_t dst = sb + 20480 + plane * 10240 + rr * 80 + cc * 16;
        asm volatile("cp.async.cg.shared.global [%0], [%1], 16, %2;"
                     :: "r"(dst), "l"(src), "r"(16));
    }
    asm volatile("cp.async.commit_group;" ::: "memory");
}

__device__ __forceinline__ void compute_stage(uint32_t sb, int warp_m, int warp_n,
                                              int lane, float acc[2][8][4]) {
    int quad = lane >> 3, lr = lane & 7;
    int rowA = ((quad & 1) << 3) + lr;
    int colA = (quad & 2) ? 8 : 0;
    int rowB = ((quad >> 1) << 3) + lr;
    int colB = (quad & 1) ? 8 : 0;
#pragma unroll
    for (int step = 0; step < 2; step++) {
        int kb = step * 16;
        uint32_t ahi[2][4], alo[2][4], bhi[8][2], blo[8][2];
#pragma unroll
        for (int mt = 0; mt < 2; mt++) {
            uint32_t ah = sb + (warp_m * 32 + mt * 16 + rowA) * 80 + (kb + colA) * 2;
            ldsm4(ahi[mt], ah);
            ldsm4(alo[mt], ah + 10240);
        }
#pragma unroll
        for (int np = 0; np < 4; np++) {
            uint32_t bh = sb + 20480 + (warp_n * 64 + np * 16 + rowB) * 80 + (kb + colB) * 2;
            uint32_t r[4];
            ldsm4(r, bh);
            bhi[np * 2][0] = r[0]; bhi[np * 2][1] = r[1];
            bhi[np * 2 + 1][0] = r[2]; bhi[np * 2 + 1][1] = r[3];
            ldsm4(r, bh + 10240);
            blo[np * 2][0] = r[0]; blo[np * 2][1] = r[1];
            blo[np * 2 + 1][0] = r[2]; blo[np * 2 + 1][1] = r[3];
        }
#pragma unroll
        for (int mt = 0; mt < 2; mt++)
#pragma unroll
            for (int nt = 0; nt < 8; nt++) {
                mma16816(acc[mt][nt], ahi[mt], bhi[nt]);
                mma16816(acc[mt][nt], alo[mt], bhi[nt]);
                mma16816(acc[mt][nt], ahi[mt], blo[nt]);
            }
    }
}

__device__ __forceinline__ void gemm_main(
    char* smc, const us* Ahi, const us* Alo,
    const us* Whi, const us* Wlo,
    int bm, int bn, float acc[2][8][4])
{
#pragma unroll
    for (int a = 0; a < 2; a++)
#pragma unroll
        for (int b = 0; b < 8; b++)
#pragma unroll
            for (int c = 0; c < 4; c++) acc[a][b][c] = 0.0f;

    uint32_t sb = smem_u32(smc);
    int lane = threadIdx.x & 31, wid = threadIdx.x >> 5;
    int warp_m = wid & 3, warp_n = wid >> 2;

    issue_stage(sb, Ahi, Alo, Whi, Wlo, bm, bn, 0);
    for (int s = 0; s < 8; s++) {
        if (s < 7) {
            issue_stage(sb + ((s + 1) & 1) * STG, Ahi, Alo, Whi, Wlo, bm, bn, (s + 1) * 32);
            asm volatile("cp.async.wait_group 1;" ::: "memory");
        } else {
            asm volatile("cp.async.wait_group 0;" ::: "memory");
        }
        __syncthreads();
        compute_stage(sb + (s & 1) * STG, warp_m, warp_n, lane, acc);
        __syncthreads();
    }
}

// ---------------- normal GEMM (fp16 output) ----------------------------------
__global__ __launch_bounds__(256)
void k_gemm_h(const us* __restrict__ Ahi, const us* __restrict__ Alo,
              const us* __restrict__ Whi, const us* __restrict__ Wlo,
              __half* __restrict__ C, int ldc) {
    extern __shared__ char smc[];
    int bm = blockIdx.x * 128, bn = blockIdx.y * 128;
    float acc[2][8][4];
    gemm_main(smc, Ahi, Alo, Whi, Wlo, bm, bn, acc);
    int lane = threadIdx.x & 31, wid = threadIdx.x >> 5;
    int g = lane >> 2, tig = lane & 3;
#pragma unroll
    for (int mt = 0; mt < 2; mt++) {
        int row0 = bm + (wid & 3) * 32 + mt * 16 + g;
#pragma unroll
        for (int nt = 0; nt < 8; nt++) {
            int col = bn + (wid >> 2) * 64 + nt * 8 + tig * 2;
            if (row0 < MM)
                *(__half2*)(C + (size_t)row0 * ldc + col) =
                    __floats2half2_rn(acc[mt][nt][0], acc[mt][nt][1]);
            if (row0 + 8 < MM)
                *(__half2*)(C + (size_t)(row0 + 8) * ldc + col) =
                    __floats2half2_rn(acc[mt][nt][2], acc[mt][nt][3]);
        }
    }
}

// ---------------- GEMM (sumg @ Wh2^T) with fused GRU update ------------------
__device__ __forceinline__ void gru2(int row, int col, float a0, float a1,
                                     const float* __restrict__ bz,
                                     const float* __restrict__ bh,
                                     float* __restrict__ Hout) {
    if (row >= MM) return;
    size_t o768 = (size_t)row * 768 + col;
    size_t o256 = (size_t)row * 256 + col;
    float2 xz = __half22float2(*(const __half2*)(g_x3 + o768));
    float2 xh = __half22float2(*(const __half2*)(g_x3 + o768 + 512));
    float2 zl = __half22float2(*(const __half2*)(g_zlin + o256));
    us2 shh = *(const us2*)(g_shhi + o256);
    us2 shl = *(const us2*)(g_shlo + o256);
    float2 bzv = *(const float2*)(bz + col);
    float2 bhv = *(const float2*)(bh + col);
    float sh0 = join_bf(shh.x, shl.x);
    float sh1 = join_bf(shh.y, shl.y);
    float z0 = sigmf(xz.x + zl.x + bzv.x);
    float p0 = tanhf(xh.x + a0 + bhv.x);
    float o0 = (1.0f - z0) * sh0 + z0 * p0;
    float z1 = sigmf(xz.y + zl.y + bzv.y);
    float p1 = tanhf(xh.y + a1 + bhv.y);
    float o1 = (1.0f - z1) * sh1 + z1 * p1;
    if (row == 0) { o0 = 0.0f; o1 = 0.0f; }
    *(float2*)(Hout + o256) = make_float2(o0, o1);
    us2 hi, lo;
    split_bf(o0, hi.x, lo.x); split_bf(o1, hi.y, lo.y);
    *(us2*)(g_hhi + o256) = hi;
    *(us2*)(g_hlo + o256) = lo;
}

__global__ __launch_bounds__(256)
void k_gemm_gru(const us* __restrict__ Ahi, const us* __restrict__ Alo,
                const us* __restrict__ Whi, const us* __restrict__ Wlo,
                float* __restrict__ Hout, const float* __restrict__ bz,
                const float* __restrict__ bh) {
    extern __shared__ char smc[];
    int bm = blockIdx.x * 128, bn = blockIdx.y * 128;
    float acc[2][8][4];
    gemm_main(smc, Ahi, Alo, Whi, Wlo, bm, bn, acc);
    int lane = threadIdx.x & 31, wid = threadIdx.x >> 5;
    int g = lane >> 2, tig = lane & 3;
#pragma unroll
    for (int mt = 0; mt < 2; mt++) {
        int row0 = bm + (wid & 3) * 32 + mt * 16 + g;
#pragma unroll
        for (int nt = 0; nt < 8; nt++) {
            int col = bn + (wid >> 2) * 64 + nt * 8 + tig * 2;
            gru2(row0, col, acc[mt][nt][0], acc[mt][nt][1], bz, bh, Hout);
            gru2(row0 + 8, col, acc[mt][nt][2], acc[mt][nt][3], bz, bh, Hout);
        }
    }
}

// ---------------------------------------------------------------------------
// first GRU step (h == 0)
// ---------------------------------------------------------------------------
__global__ void k_first(float* __restrict__ h, const float* __restrict__ bz,
                        const float* __restrict__ bh) {
    int e = blockIdx.x * blockDim.x + threadIdx.x;
    if (e >= MM * 64) return;
    int m = e >> 6, c = (e & 63) * 4;
    const __half2* xzp = (const __half2*)(g_x3 + (size_t)m * 768 + c);
    const __half2* xhp = (const __half2*)(g_x3 + (size_t)m * 768 + 512 + c);
    float2 xz0 = __half22float2(xzp[0]), xz1 = __half22float2(xzp[1]);
    float2 xh0 = __half22float2(xhp[0]), xh1 = __half22float2(xhp[1]);
    float4 bzv = *(const float4*)(bz + c);
    float4 bhv = *(const float4*)(bh + c);
    float4 o;
    o.x = sigmf(xz0.x + bzv.x) * tanhf(xh0.x + bhv.x);
    o.y = sigmf(xz0.y + bzv.y) * tanhf(xh0.y + bhv.y);
    o.z = sigmf(xz1.x + bzv.z) * tanhf(xh1.x + bhv.z);
    o.w = sigmf(xz1.y + bzv.w) * tanhf(xh1.y + bhv.w);
    if (m == 0) o = make_float4(0.f, 0.f, 0.f, 0.f);
    *(float4*)(h + (size_t)m * HH + c) = o;
    us4 hi, lo;
    split_bf(o.x, hi.x, lo.x); split_bf(o.y, hi.y, lo.y);
    split_bf(o.z, hi.z, lo.z); split_bf(o.w, hi.w, lo.w);
    *(us4*)(g_hhi + (size_t)m * HH + c) = hi;
    *(us4*)(g_hlo + (size_t)m * HH + c) = lo;
}

// ---------------------------------------------------------------------------
// gather: sum_h (planes) and sum(r*h_nei) (planes); h read fp32, hUr fp16
// ---------------------------------------------------------------------------
__global__ void k_gather(const float* __restrict__ h, const int* __restrict__ mg,
                         const float* __restrict__ bu) {
    int m = blockIdx.x * blockDim.y + threadIdx.y;
    if (m >= MM) return;
    int c = threadIdx.x * 4;
    int idx[KK];
#pragma unroll
    for (int k = 0; k < KK; k++) idx[k] = mg[m * KK + k];
    const __half2* xrp = (const __half2*)(g_x3 + (size_t)m * 768 + 256 + c);
    float2 xr0 = __half22float2(xrp[0]), xr1 = __half22float2(xrp[1]);
    float4 bv = *(const float4*)(bu + c);
    float4 as = make_float4(0.f, 0.f, 0.f, 0.f);
    float4 ag = make_float4(0.f, 0.f, 0.f, 0.f);
#pragma unroll
    for (int k = 0; k < KK; k++) {
        const float4 hv = *(const float4*)(h + (size_t)idx[k] * HH + c);
        const __half2* up = (const __half2*)(g_hUr + (size_t)idx[k] * HH + c);
        float2 u0 = __half22float2(up[0]);
        float2 u1 = __half22float2(up[1]);
        float rx = sigmf(xr0.x + u0.x + bv.x);
        float ry = sigmf(xr0.y + u0.y + bv.y);
        float rz = sigmf(xr1.x + u1.x + bv.z);
        float rw = sigmf(xr1.y + u1.y + bv.w);
        as.x += hv.x; as.y += hv.y; as.z += hv.z; as.w += hv.w;
        ag.x = fmaf(rx, hv.x, ag.x); ag.y = fmaf(ry, hv.y, ag.y);
        ag.z = fmaf(rz, hv.z, ag.z); ag.w = fmaf(rw, hv.w, ag.w);
    }
    us4 hi, lo;
    split_bf(as.x, hi.x, lo.x); split_bf(as.y, hi.y, lo.y);
    split_bf(as.z, hi.z, lo.z); split_bf(as.w, hi.w, lo.w);
    *(us4*)(g_shhi + (size_t)m * HH + c) = hi;
    *(us4*)(g_shlo + (size_t)m * HH + c) = lo;
    split_bf(ag.x, hi.x, lo.x); split_bf(ag.y, hi.y, lo.y);
    split_bf(ag.z, hi.z, lo.z); split_bf(ag.w, hi.w, lo.w);
    *(us4*)(g_sghi + (size_t)m * HH + c) = hi;
    *(us4*)(g_sglo + (size_t)m * HH + c) = lo;
}

// ---------------------------------------------------------------------------
// readout (B=64 roots)
// ---------------------------------------------------------------------------
__global__ void k_readout(const int* __restrict__ scope_st, const int* __restrict__ fnode,
                          const int* __restrict__ node_graph, const float* __restrict__ emb,
                          const float* __restrict__ h, const float* __restrict__ Wo,
                          const float* __restrict__ bo, float* __restrict__ out) {
    __shared__ float fe[HH];
    __shared__ float mn[HH];
    int b = blockIdx.x, j = threadIdx.x;
    int n = scope_st[b];
    fe[j] = emb[(size_t)fnode[n] * HH + j];
    float s = 0.0f;
#pragma unroll
    for (int k = 0; k < KK; k++) s += h[(size_t)node_graph[n * KK + k] * HH + j];
    mn[j] = s;
    __syncthreads();
    float acc = bo[j];
    const float* wrow = Wo + (size_t)j * 512;
#pragma unroll 4
    for (int i = 0; i < 256; i += 4) {
        float4 w = *(const float4*)(wrow + i);
        float4 f = *(const float4*)&fe[i];
        acc = fmaf(w.x, f.x, acc); acc = fmaf(w.y, f.y, acc);
        acc = fmaf(w.z, f.z, acc); acc = fmaf(w.w, f.w, acc);
    }
#pragma unroll 4
    for (int i = 0; i < 256; i += 4) {
        float4 w = *(const float4*)(wrow + 256 + i);
        float4 f = *(const float4*)&mn[i];
        acc = fmaf(w.x, f.x, acc); acc = fmaf(w.y, f.y, acc);
        acc = fmaf(w.z, f.z, acc); acc = fmaf(w.w, f.w, acc);
    }
    out[(size_t)b * HH + j] = fmaxf(acc, 0.0f);
}

// ---------------------------------------------------------------------------
// launch
// ---------------------------------------------------------------------------
extern "C" void kernel_launch(void* const* d_in, const int* in_sizes, int n_in,
                              void* d_out, int out_size) {
    const int*   fnode      = (const int*)  d_in[0];
    const int*   fmess      = (const int*)  d_in[1];
    const int*   node_graph = (const int*)  d_in[2];
    const int*   mess_graph = (const int*)  d_in[3];
    const int*   scope_st   = (const int*)  d_in[4];
    const float* emb        = (const float*)d_in[5];
    const float* Wz         = (const float*)d_in[6];
    const float* bz         = (const float*)d_in[7];
    const float* Wr         = (const float*)d_in[8];
    const float* Ur         = (const float*)d_in[9];
    const float* bu         = (const float*)d_in[10];
    const float* Wh         = (const float*)d_in[11];
    const float* bh         = (const float*)d_in[12];
    const float* Wo         = (const float*)d_in[13];
    const float* bo         = (const float*)d_in[14];

    float* out = (float*)d_out;
    float* h = out + (size_t)BB * HH;

    cudaFuncSetAttribute(k_gemm_h,   cudaFuncAttributeMaxDynamicSharedMemorySize, SMEM_GEMM);
    cudaFuncSetAttribute(k_gemm_gru, cudaFuncAttributeMaxDynamicSharedMemorySize, SMEM_GEMM);

    us *xhi, *xlo, *hhi, *hlo, *shhi, *shlo, *sghi, *sglo;
    us *Wprehi, *Wprelo, *Wz2hi, *Wz2lo, *Wh2hi, *Wh2lo, *Urhi, *Urlo;
    __half *x3p, *hUrp, *zlinp;
    cudaGetSymbolAddress((void**)&xhi, g_xhi);   cudaGetSymbolAddress((void**)&xlo, g_xlo);
    cudaGetSymbolAddress((void**)&hhi, g_hhi);   cudaGetSymbolAddress((void**)&hlo, g_hlo);
    cudaGetSymbolAddress((void**)&shhi, g_shhi); cudaGetSymbolAddress((void**)&shlo, g_shlo);
    cudaGetSymbolAddress((void**)&sghi, g_sghi); cudaGetSymbolAddress((void**)&sglo, g_sglo);
    cudaGetSymbolAddress((void**)&Wprehi, g_Wprehi); cudaGetSymbolAddress((void**)&Wprelo, g_Wprelo);
    cudaGetSymbolAddress((void**)&Wz2hi, g_Wz2hi);   cudaGetSymbolAddress((void**)&Wz2lo, g_Wz2lo);
    cudaGetSymbolAddress((void**)&Wh2hi, g_Wh2hi);   cudaGetSymbolAddress((void**)&Wh2lo, g_Wh2lo);
    cudaGetSymbolAddress((void**)&Urhi, g_Urhi);     cudaGetSymbolAddress((void**)&Urlo, g_Urlo);
    cudaGetSymbolAddress((void**)&x3p, g_x3);
    cudaGetSymbolAddress((void**)&zlinp, g_zlin);
    cudaGetSymbolAddress((void**)&hUrp, g_hUr);

    const int ETH = 256;
    const int EBL = (MM * 64 + ETH - 1) / ETH;
    const int MT  = (MM + 127) / 128;

    k_pack <<<1536, 256>>>(Wz, Wr, Wh, Ur);
    k_embed<<<EBL, ETH>>>(fnode, fmess, emb);

    k_gemm_h<<<dim3(MT, 6), 256, SMEM_GEMM>>>(xhi, xlo, Wprehi, Wprelo, x3p, 768);
    k_first<<<EBL, ETH>>>(h, bz, bh);

    for (int it = 1; it < NDEPTH; it++) {
        k_gemm_h<<<dim3(MT, 2), 256, SMEM_GEMM>>>(hhi, hlo, Urhi, Urlo, hUrp, 256);
        k_gather<<<(MM + 3) / 4, dim3(64, 4)>>>(h, mess_graph, bu);
        k_gemm_h<<<dim3(MT, 2), 256, SMEM_GEMM>>>(shhi, shlo, Wz2hi, Wz2lo, zlinp, 256);
        k_gemm_gru<<<dim3(MT, 2), 256, SMEM_GEMM>>>(sghi, sglo, Wh2hi, Wh2lo, h, bz, bh);
    }

    k_readout<<<BB, HH>>>(scope_st, fnode, node_graph, emb, h, Wo, bo, out);
}

// round 15
// speedup vs baseline: 1.5732x; 1.0542x over previous
#include <cuda_runtime.h>
#include <cuda_bf16.h>
#include <cuda_fp16.h>
#include <math.h>
#include <stdint.h>

#define MM 100001
#define NN 50000
#define VV 780
#define HH 256
#define KK 6
#define BB 64
#define NDEPTH 6

typedef unsigned short us;

// ---------------------------------------------------------------------------
// scratch
// ---------------------------------------------------------------------------
__device__ __align__(16) us g_hhi[(size_t)MM * HH];
__device__ __align__(16) us g_hlo[(size_t)MM * HH];
__device__ __align__(16) us g_shhi[(size_t)MM * HH];
__device__ __align__(16) us g_shlo[(size_t)MM * HH];
__device__ __align__(16) us g_sghi[(size_t)MM * HH];
__device__ __align__(16) us g_sglo[(size_t)MM * HH];
__device__ __align__(16) __half g_hUr [(size_t)MM * HH];
__device__ __align__(16) __half g_zlin[(size_t)MM * HH];
__device__ int g_vid[MM];
__device__ __align__(16) float g_emb3[(size_t)VV * 768];   // emb @ [Wz1;Wr;Wh1]^T
__device__ __align__(16) us g_embhi[VV * 256];
__device__ __align__(16) us g_emblo[VV * 256];
__device__ __align__(16) us g_Wprehi[768 * 256];
__device__ __align__(16) us g_Wprelo[768 * 256];
__device__ __align__(16) us g_Wz2hi[256 * 256];
__device__ __align__(16) us g_Wz2lo[256 * 256];
__device__ __align__(16) us g_Wh2hi[256 * 256];
__device__ __align__(16) us g_Wh2lo[256 * 256];
__device__ __align__(16) us g_Urhi[256 * 256];
__device__ __align__(16) us g_Urlo[256 * 256];

__device__ __forceinline__ float sigmf(float v) { return 1.0f / (1.0f + expf(-v)); }
__device__ __forceinline__ void split_bf(float v, us& hi, us& lo) {
    __nv_bfloat16 h = __float2bfloat16(v);
    __nv_bfloat16 l = __float2bfloat16(v - __bfloat162float(h));
    hi = *(us*)&h; lo = *(us*)&l;
}
__device__ __forceinline__ float join_bf(us hi, us lo) {
    return __bfloat162float(*(__nv_bfloat16*)&hi) + __bfloat162float(*(__nv_bfloat16*)&lo);
}
struct us2 { us x, y; };
struct us4 { us x, y, z, w; };

__device__ __forceinline__ uint32_t smem_u32(const void* p) {
    uint32_t a;
    asm("{ .reg .u64 t; cvta.to.shared.u64 t, %1; cvt.u32.u64 %0, t; }" : "=r"(a) : "l"(p));
    return a;
}
__device__ __forceinline__ void ldsm4(uint32_t* r, uint32_t addr) {
    asm volatile("ldmatrix.sync.aligned.m8n8.x4.shared.b16 {%0,%1,%2,%3}, [%4];"
        : "=r"(r[0]), "=r"(r[1]), "=r"(r[2]), "=r"(r[3]) : "r"(addr));
}
__device__ __forceinline__ void mma16816(float* d, const uint32_t* a, const uint32_t* b) {
    asm volatile("mma.sync.aligned.m16n8k16.row.col.f32.bf16.bf16.f32 "
        "{%0,%1,%2,%3}, {%4,%5,%6,%7}, {%8,%9}, {%0,%1,%2,%3};"
        : "+f"(d[0]), "+f"(d[1]), "+f"(d[2]), "+f"(d[3])
        : "r"(a[0]), "r"(a[1]), "r"(a[2]), "r"(a[3]), "r"(b[0]), "r"(b[1]));
}

// ---------------------------------------------------------------------------
// weight pack + split
// ---------------------------------------------------------------------------
__global__ void k_pack(const float* __restrict__ Wz, const float* __restrict__ Wr,
                       const float* __restrict__ Wh, const float* __restrict__ Ur) {
    int idx = blockIdx.x * blockDim.x + threadIdx.x;
    int j = idx >> 8, i = idx & 255;
    float v; us hi, lo;
    if (j < 256)       v = Wz[j * 512 + i];
    else if (j < 512)  v = Wr[(j - 256) * 256 + i];
    else if (j < 768)  v = Wh[(j - 512) * 512 + i];
    else if (j < 1024) v = Wz[(j - 768) * 512 + 256 + i];
    else if (j < 1280) v = Wh[(j - 1024) * 512 + 256 + i];
    else               v = Ur[(j - 1280) * 256 + i];
    split_bf(v, hi, lo);
    if (j < 768)        { g_Wprehi[j * 256 + i] = hi;          g_Wprelo[j * 256 + i] = lo; }
    else if (j < 1024)  { g_Wz2hi[(j - 768) * 256 + i] = hi;   g_Wz2lo[(j - 768) * 256 + i] = lo; }
    else if (j < 1280)  { g_Wh2hi[(j - 1024) * 256 + i] = hi;  g_Wh2lo[(j - 1024) * 256 + i] = lo; }
    else                { g_Urhi[(j - 1280) * 256 + i] = hi;   g_Urlo[(j - 1280) * 256 + i] = lo; }
}

// split emb (V x 256) into bf16 planes
__global__ void k_packemb(const float* __restrict__ emb) {
    int idx = blockIdx.x * blockDim.x + threadIdx.x;
    if (idx >= VV * 256) return;
    us hi, lo;
    split_bf(emb[idx], hi, lo);
    g_embhi[idx] = hi; g_emblo[idx] = lo;
}

// vid[m] = fnode[fmess[m]]
__global__ void k_vid(const int* __restrict__ fnode, const int* __restrict__ fmess) {
    int m = blockIdx.x * blockDim.x + threadIdx.x;
    if (m < MM) g_vid[m] = fnode[fmess[m]];
}

// ===========================================================================
// split-bf16 mma.sync GEMM (R4 core): CTA 128x128, 8 warps, warp tile 32x64,
// k-chunk 32, 2-stage cp.async, rows stride 80B. Mrows parametrized.
// ===========================================================================
#define STG 40960
#define SMEM_GEMM (2 * STG)

__device__ __forceinline__ void issue_stage(
    uint32_t sb, const us* __restrict__ Ahi, const us* __restrict__ Alo,
    const us* __restrict__ Bhi, const us* __restrict__ Blo,
    int bm, int bn, int kc, int Mrows)
{
    int tid = threadIdx.x;
#pragma unroll
    for (int i = 0; i < 4; i++) {           // A planes
        int v = tid + i * 256;
        int plane = v >> 9, w = v & 511;
        int rr = w >> 2, cc = w & 3;
        int row = bm + rr;
        int sz = (row < Mrows) ? 16 : 0;
        const us* src = (plane ? Alo : Ahi) +
            (size_t)(row < Mrows ? row : 0) * 256 + kc + cc * 8;
        uint32_t dst = sb + plane * 10240 + rr * 80 + cc * 16;
        asm volatile("cp.async.cg.shared.global [%0], [%1], 16, %2;"
                     :: "r"(dst), "l"(src), "r"(sz));
    }
#pragma unroll
    for (int i = 0; i < 4; i++) {           // B planes
        int v = tid + i * 256;
        int plane = v >> 9, w = v & 511;
        int rr = w >> 2, cc = w & 3;
        const us* src = (plane ? Blo : Bhi) + (size_t)(bn + rr) * 256 + kc + cc * 8;
        uint32_t dst = sb + 20480 + plane * 10240 + rr * 80 + cc * 16;
        asm volatile("cp.async.cg.shared.global [%0], [%1], 16, %2;"
                     :: "r"(dst), "l"(src), "r"(16));
    }
    asm volatile("cp.async.commit_group;" ::: "memory");
}

__device__ __forceinline__ void compute_stage(uint32_t sb, int warp_m, int warp_n,
                                              int lane, float acc[2][8][4]) {
    int quad = lane >> 3, lr = lane & 7;
    int rowA = ((quad & 1) << 3) + lr;
    int colA = (quad & 2) ? 8 : 0;
    int rowB = ((quad >> 1) << 3) + lr;
    int colB = (quad & 1) ? 8 : 0;
#pragma unroll
    for (int step = 0; step < 2; step++) {
        int kb = step * 16;
        uint32_t ahi[2][4], alo[2][4], bhi[8][2], blo[8][2];
#pragma unroll
        for (int mt = 0; mt < 2; mt++) {
            uint32_t ah = sb + (warp_m * 32 + mt * 16 + rowA) * 80 + (kb + colA) * 2;
            ldsm4(ahi[mt], ah);
            ldsm4(alo[mt], ah + 10240);
        }
#pragma unroll
        for (int np = 0; np < 4; np++) {
            uint32_t bh = sb + 20480 + (warp_n * 64 + np * 16 + rowB) * 80 + (kb + colB) * 2;
            uint32_t r[4];
            ldsm4(r, bh);
            bhi[np * 2][0] = r[0]; bhi[np * 2][1] = r[1];
            bhi[np * 2 + 1][0] = r[2]; bhi[np * 2 + 1][1] = r[3];
            ldsm4(r, bh + 10240);
            blo[np * 2][0] = r[0]; blo[np * 2][1] = r[1];
            blo[np * 2 + 1][0] = r[2]; blo[np * 2 + 1][1] = r[3];
        }
#pragma unroll
        for (int mt = 0; mt < 2; mt++)
#pragma unroll
            for (int nt = 0; nt < 8; nt++) {
                mma16816(acc[mt][nt], ahi[mt], bhi[nt]);
                mma16816(acc[mt][nt], alo[mt], bhi[nt]);
                mma16816(acc[mt][nt], ahi[mt], blo[nt]);
            }
    }
}

__device__ __forceinline__ void gemm_main(
    char* smc, const us* Ahi, const us* Alo,
    const us* Whi, const us* Wlo,
    int bm, int bn, int Mrows, float acc[2][8][4])
{
#pragma unroll
    for (int a = 0; a < 2; a++)
#pragma unroll
        for (int b = 0; b < 8; b++)
#pragma unroll
            for (int c = 0; c < 4; c++) acc[a][b][c] = 0.0f;

    uint32_t sb = smem_u32(smc);
    int lane = threadIdx.x & 31, wid = threadIdx.x >> 5;
    int warp_m = wid & 3, warp_n = wid >> 2;

    issue_stage(sb, Ahi, Alo, Whi, Wlo, bm, bn, 0, Mrows);
    for (int s = 0; s < 8; s++) {
        if (s < 7) {
            issue_stage(sb + ((s + 1) & 1) * STG, Ahi, Alo, Whi, Wlo, bm, bn, (s + 1) * 32, Mrows);
            asm volatile("cp.async.wait_group 1;" ::: "memory");
        } else {
            asm volatile("cp.async.wait_group 0;" ::: "memory");
        }
        __syncthreads();
        compute_stage(sb + (s & 1) * STG, warp_m, warp_n, lane, acc);
        __syncthreads();
    }
}

// ---------------- GEMM with fp16 output --------------------------------------
__global__ __launch_bounds__(256)
void k_gemm_h(const us* __restrict__ Ahi, const us* __restrict__ Alo,
              const us* __restrict__ Whi, const us* __restrict__ Wlo,
              __half* __restrict__ C, int Mrows, int ldc) {
    extern __shared__ char smc[];
    int bm = blockIdx.x * 128, bn = blockIdx.y * 128;
    float acc[2][8][4];
    gemm_main(smc, Ahi, Alo, Whi, Wlo, bm, bn, Mrows, acc);
    int lane = threadIdx.x & 31, wid = threadIdx.x >> 5;
    int g = lane >> 2, tig = lane & 3;
#pragma unroll
    for (int mt = 0; mt < 2; mt++) {
        int row0 = bm + (wid & 3) * 32 + mt * 16 + g;
#pragma unroll
        for (int nt = 0; nt < 8; nt++) {
            int col = bn + (wid >> 2) * 64 + nt * 8 + tig * 2;
            if (row0 < Mrows)
                *(__half2*)(C + (size_t)row0 * ldc + col) =
                    __floats2half2_rn(acc[mt][nt][0], acc[mt][nt][1]);
            if (row0 + 8 < Mrows)
                *(__half2*)(C + (size_t)(row0 + 8) * ldc + col) =
                    __floats2half2_rn(acc[mt][nt][2], acc[mt][nt][3]);
        }
    }
}

// ---------------- GEMM with fp32 output (for emb3) ---------------------------
__global__ __launch_bounds__(256)
void k_gemm_f(const us* __restrict__ Ahi, const us* __restrict__ Alo,
              const us* __restrict__ Whi, const us* __restrict__ Wlo,
              float* __restrict__ C, int Mrows, int ldc) {
    extern __shared__ char smc[];
    int bm = blockIdx.x * 128, bn = blockIdx.y * 128;
    float acc[2][8][4];
    gemm_main(smc, Ahi, Alo, Whi, Wlo, bm, bn, Mrows, acc);
    int lane = threadIdx.x & 31, wid = threadIdx.x >> 5;
    int g = lane >> 2, tig = lane & 3;
#pragma unroll
    for (int mt = 0; mt < 2; mt++) {
        int row0 = bm + (wid & 3) * 32 + mt * 16 + g;
#pragma unroll
        for (int nt = 0; nt < 8; nt++) {
            int col = bn + (wid >> 2) * 64 + nt * 8 + tig * 2;
            if (row0 < Mrows)
                *(float2*)(C + (size_t)row0 * ldc + col) =
                    make_float2(acc[mt][nt][0], acc[mt][nt][1]);
            if (row0 + 8 < Mrows)
                *(float2*)(C + (size_t)(row0 + 8) * ldc + col) =
                    make_float2(acc[mt][nt][2], acc[mt][nt][3]);
        }
    }
}

// ---------------- GEMM (sumg @ Wh2^T) with fused GRU update ------------------
__device__ __forceinline__ void gru2(int row, int col, float a0, float a1,
                                     const float* __restrict__ bz,
                                     const float* __restrict__ bh,
                                     float* __restrict__ Hout) {
    if (row >= MM) return;
    size_t e768 = (size_t)g_vid[row] * 768 + col;
    size_t o256 = (size_t)row * 256 + col;
    float2 xz = *(const float2*)(g_emb3 + e768);
    float2 xh = *(const float2*)(g_emb3 + e768 + 512);
    float2 zl = __half22float2(*(const __half2*)(g_zlin + o256));
    us2 shh = *(const us2*)(g_shhi + o256);
    us2 shl = *(const us2*)(g_shlo + o256);
    float2 bzv = *(const float2*)(bz + col);
    float2 bhv = *(const float2*)(bh + col);
    float sh0 = join_bf(shh.x, shl.x);
    float sh1 = join_bf(shh.y, shl.y);
    float z0 = sigmf(xz.x + zl.x + bzv.x);
    float p0 = tanhf(xh.x + a0 + bhv.x);
    float o0 = (1.0f - z0) * sh0 + z0 * p0;
    float z1 = sigmf(xz.y + zl.y + bzv.y);
    float p1 = tanhf(xh.y + a1 + bhv.y);
    float o1 = (1.0f - z1) * sh1 + z1 * p1;
    if (row == 0) { o0 = 0.0f; o1 = 0.0f; }
    *(float2*)(Hout + o256) = make_float2(o0, o1);
    us2 hi, lo;
    split_bf(o0, hi.x, lo.x); split_bf(o1, hi.y, lo.y);
    *(us2*)(g_hhi + o256) = hi;
    *(us2*)(g_hlo + o256) = lo;
}

__global__ __launch_bounds__(256)
void k_gemm_gru(const us* __restrict__ Ahi, const us* __restrict__ Alo,
                const us* __restrict__ Whi, const us* __restrict__ Wlo,
                float* __restrict__ Hout, const float* __restrict__ bz,
                const float* __restrict__ bh) {
    extern __shared__ char smc[];
    int bm = blockIdx.x * 128, bn = blockIdx.y * 128;
    float acc[2][8][4];
    gemm_main(smc, Ahi, Alo, Whi, Wlo, bm, bn, MM, acc);
    int lane = threadIdx.x & 31, wid = threadIdx.x >> 5;
    int g = lane >> 2, tig = lane & 3;
#pragma unroll
    for (int mt = 0; mt < 2; mt++) {
        int row0 = bm + (wid & 3) * 32 + mt * 16 + g;
#pragma unroll
        for (int nt = 0; nt < 8; nt++) {
            int col = bn + (wid >> 2) * 64 + nt * 8 + tig * 2;
            gru2(row0, col, acc[mt][nt][0], acc[mt][nt][1], bz, bh, Hout);
            gru2(row0 + 8, col, acc[mt][nt][2], acc[mt][nt][3], bz, bh, Hout);
        }
    }
}

// ---------------------------------------------------------------------------
// first GRU step (h == 0): x terms from emb3[vid]
// ---------------------------------------------------------------------------
__global__ void k_first(float* __restrict__ h, const float* __restrict__ bz,
                        const float* __restrict__ bh) {
    int e = blockIdx.x * blockDim.x + threadIdx.x;
    if (e >= MM * 64) return;
    int m = e >> 6, c = (e & 63) * 4;
    size_t e768 = (size_t)g_vid[m] * 768 + c;
    float4 xz = *(const float4*)(g_emb3 + e768);
    float4 xh = *(const float4*)(g_emb3 + e768 + 512);
    float4 bzv = *(const float4*)(bz + c);
    float4 bhv = *(const float4*)(bh + c);
    float4 o;
    o.x = sigmf(xz.x + bzv.x) * tanhf(xh.x + bhv.x);
    o.y = sigmf(xz.y + bzv.y) * tanhf(xh.y + bhv.y);
    o.z = sigmf(xz.z + bzv.z) * tanhf(xh.z + bhv.z);
    o.w = sigmf(xz.w + bzv.w) * tanhf(xh.w + bhv.w);
    if (m == 0) o = make_float4(0.f, 0.f, 0.f, 0.f);
    *(float4*)(h + (size_t)m * HH + c) = o;
    us4 hi, lo;
    split_bf(o.x, hi.x, lo.x); split_bf(o.y, hi.y, lo.y);
    split_bf(o.z, hi.z, lo.z); split_bf(o.w, hi.w, lo.w);
    *(us4*)(g_hhi + (size_t)m * HH + c) = hi;
    *(us4*)(g_hlo + (size_t)m * HH + c) = lo;
}

// ---------------------------------------------------------------------------
// gather: sum_h (planes) and sum(r*h_nei) (planes); h fp32, hUr fp16, xr L2
// ---------------------------------------------------------------------------
__global__ void k_gather(const float* __restrict__ h, const int* __restrict__ mg,
                         const float* __restrict__ bu) {
    int m = blockIdx.x * blockDim.y + threadIdx.y;
    if (m >= MM) return;
    int c = threadIdx.x * 4;
    int idx[KK];
#pragma unroll
    for (int k = 0; k < KK; k++) idx[k] = mg[m * KK + k];
    float4 xr = *(const float4*)(g_emb3 + (size_t)g_vid[m] * 768 + 256 + c);
    float4 bv = *(const float4*)(bu + c);
    float4 as = make_float4(0.f, 0.f, 0.f, 0.f);
    float4 ag = make_float4(0.f, 0.f, 0.f, 0.f);
#pragma unroll
    for (int k = 0; k < KK; k++) {
        const float4 hv = *(const float4*)(h + (size_t)idx[k] * HH + c);
        const __half2* up = (const __half2*)(g_hUr + (size_t)idx[k] * HH + c);
        float2 u0 = __half22float2(up[0]);
        float2 u1 = __half22float2(up[1]);
        float rx = sigmf(xr.x + u0.x + bv.x);
        float ry = sigmf(xr.y + u0.y + bv.y);
        float rz = sigmf(xr.z + u1.x + bv.z);
        float rw = sigmf(xr.w + u1.y + bv.w);
        as.x += hv.x; as.y += hv.y; as.z += hv.z; as.w += hv.w;
        ag.x = fmaf(rx, hv.x, ag.x); ag.y = fmaf(ry, hv.y, ag.y);
        ag.z = fmaf(rz, hv.z, ag.z); ag.w = fmaf(rw, hv.w, ag.w);
    }
    us4 hi, lo;
    split_bf(as.x, hi.x, lo.x); split_bf(as.y, hi.y, lo.y);
    split_bf(as.z, hi.z, lo.z); split_bf(as.w, hi.w, lo.w);
    *(us4*)(g_shhi + (size_t)m * HH + c) = hi;
    *(us4*)(g_shlo + (size_t)m * HH + c) = lo;
    split_bf(ag.x, hi.x, lo.x); split_bf(ag.y, hi.y, lo.y);
    split_bf(ag.z, hi.z, lo.z); split_bf(ag.w, hi.w, lo.w);
    *(us4*)(g_sghi + (size_t)m * HH + c) = hi;
    *(us4*)(g_sglo + (size_t)m * HH + c) = lo;
}

// ---------------------------------------------------------------------------
// readout (B=64 roots)
// ---------------------------------------------------------------------------
__global__ void k_readout(const int* __restrict__ scope_st, const int* __restrict__ fnode,
                          const int* __restrict__ node_graph, const float* __restrict__ emb,
                          const float* __restrict__ h, const float* __restrict__ Wo,
                          const float* __restrict__ bo, float* __restrict__ out) {
    __shared__ float fe[HH];
    __shared__ float mn[HH];
    int b = blockIdx.x, j = threadIdx.x;
    int n = scope_st[b];
    fe[j] = emb[(size_t)fnode[n] * HH + j];
    float s = 0.0f;
#pragma unroll
    for (int k = 0; k < KK; k++) s += h[(size_t)node_graph[n * KK + k] * HH + j];
    mn[j] = s;
    __syncthreads();
    float acc = bo[j];
    const float* wrow = Wo + (size_t)j * 512;
#pragma unroll 4
    for (int i = 0; i < 256; i += 4) {
        float4 w = *(const float4*)(wrow + i);
        float4 f = *(const float4*)&fe[i];
        acc = fmaf(w.x, f.x, acc); acc = fmaf(w.y, f.y, acc);
        acc = fmaf(w.z, f.z, acc); acc = fmaf(w.w, f.w, acc);
    }
#pragma unroll 4
    for (int i = 0; i < 256; i += 4) {
        float4 w = *(const float4*)(wrow + 256 + i);
        float4 f = *(const float4*)&mn[i];
        acc = fmaf(w.x, f.x, acc); acc = fmaf(w.y, f.y, acc);
        acc = fmaf(w.z, f.z, acc); acc = fmaf(w.w, f.w, acc);
    }
    out[(size_t)b * HH + j] = fmaxf(acc, 0.0f);
}

// ---------------------------------------------------------------------------
// launch
// ---------------------------------------------------------------------------
extern "C" void kernel_launch(void* const* d_in, const int* in_sizes, int n_in,
                              void* d_out, int out_size) {
    const int*   fnode      = (const int*)  d_in[0];
    const int*   fmess      = (const int*)  d_in[1];
    const int*   node_graph = (const int*)  d_in[2];
    const int*   mess_graph = (const int*)  d_in[3];
    const int*   scope_st   = (const int*)  d_in[4];
    const float* emb        = (const float*)d_in[5];
    const float* Wz         = (const float*)d_in[6];
    const float* bz         = (const float*)d_in[7];
    const float* Wr         = (const float*)d_in[8];
    const float* Ur         = (const float*)d_in[9];
    const float* bu         = (const float*)d_in[10];
    const float* Wh         = (const float*)d_in[11];
    const float* bh         = (const float*)d_in[12];
    const float* Wo         = (const float*)d_in[13];
    const float* bo         = (const float*)d_in[14];

    float* out = (float*)d_out;
    float* h = out + (size_t)BB * HH;

    cudaFuncSetAttribute(k_gemm_h,   cudaFuncAttributeMaxDynamicSharedMemorySize, SMEM_GEMM);
    cudaFuncSetAttribute(k_gemm_f,   cudaFuncAttributeMaxDynamicSharedMemorySize, SMEM_GEMM);
    cudaFuncSetAttribute(k_gemm_gru, cudaFuncAttributeMaxDynamicSharedMemorySize, SMEM_GEMM);

    us *hhi, *hlo, *shhi, *shlo, *sghi, *sglo, *embhi, *emblo;
    us *Wprehi, *Wprelo, *Wz2hi, *Wz2lo, *Wh2hi, *Wh2lo, *Urhi, *Urlo;
    __half *hUrp, *zlinp; float *emb3p;
    cudaGetSymbolAddress((void**)&hhi, g_hhi);   cudaGetSymbolAddress((void**)&hlo, g_hlo);
    cudaGetSymbolAddress((void**)&shhi, g_shhi); cudaGetSymbolAddress((void**)&shlo, g_shlo);
    cudaGetSymbolAddress((void**)&sghi, g_sghi); cudaGetSymbolAddress((void**)&sglo, g_sglo);
    cudaGetSymbolAddress((void**)&embhi, g_embhi); cudaGetSymbolAddress((void**)&emblo, g_emblo);
    cudaGetSymbolAddress((void**)&Wprehi, g_Wprehi); cudaGetSymbolAddress((void**)&Wprelo, g_Wprelo);
    cudaGetSymbolAddress((void**)&Wz2hi, g_Wz2hi);   cudaGetSymbolAddress((void**)&Wz2lo, g_Wz2lo);
    cudaGetSymbolAddress((void**)&Wh2hi, g_Wh2hi);   cudaGetSymbolAddress((void**)&Wh2lo, g_Wh2lo);
    cudaGetSymbolAddress((void**)&Urhi, g_Urhi);     cudaGetSymbolAddress((void**)&Urlo, g_Urlo);
    cudaGetSymbolAddress((void**)&emb3p, g_emb3);
    cudaGetSymbolAddress((void**)&zlinp, g_zlin);
    cudaGetSymbolAddress((void**)&hUrp, g_hUr);

    const int ETH = 256;
    const int EBL = (MM * 64 + ETH - 1) / ETH;
    const int MT  = (MM + 127) / 128;
    const int VT  = (VV + 127) / 128;   // 7

    k_pack   <<<1536, 256>>>(Wz, Wr, Wh, Ur);
    k_packemb<<<(VV * 256 + 255) / 256, 256>>>(emb);
    k_vid    <<<(MM + 255) / 256, 256>>>(fnode, fmess);

    // emb3 = emb @ [Wz1; Wr; Wh1]^T   (780 x 768, fp32, L2-resident)
    k_gemm_f<<<dim3(VT, 6), 256, SMEM_GEMM>>>(embhi, emblo, Wprehi, Wprelo, emb3p, VV, 768);
    k_first<<<EBL, ETH>>>(h, bz, bh);

    for (int it = 1; it < NDEPTH; it++) {
        k_gemm_h<<<dim3(MT, 2), 256, SMEM_GEMM>>>(hhi, hlo, Urhi, Urlo, hUrp, MM, 256);
        k_gather<<<(MM + 3) / 4, dim3(64, 4)>>>(h, mess_graph, bu);
        k_gemm_h<<<dim3(MT, 2), 256, SMEM_GEMM>>>(shhi, shlo, Wz2hi, Wz2lo, zlinp, MM, 256);
        k_gemm_gru<<<dim3(MT, 2), 256, SMEM_GEMM>>>(sghi, sglo, Wh2hi, Wh2lo, h, bz, bh);
    }

    k_readout<<<BB, HH>>>(scope_st, fnode, node_graph, emb, h, Wo, bo, out);
}

// round 16
// speedup vs baseline: 1.7012x; 1.0813x over previous
#include <cuda_runtime.h>
#include <cuda_bf16.h>
#include <cuda_fp16.h>
#include <math.h>
#include <stdint.h>

#define MM 100001
#define NN 50000
#define VV 780
#define HH 256
#define KK 6
#define BB 64
#define NDEPTH 6

typedef unsigned short us;

// ---------------------------------------------------------------------------
// scratch
// ---------------------------------------------------------------------------
__device__ __align__(16) us g_hhi[(size_t)MM * HH];
__device__ __align__(16) us g_hlo[(size_t)MM * HH];
__device__ __align__(16) us g_shhi[(size_t)MM * HH];
__device__ __align__(16) us g_shlo[(size_t)MM * HH];
__device__ __align__(16) us g_sghi[(size_t)MM * HH];
__device__ __align__(16) us g_sglo[(size_t)MM * HH];
__device__ __align__(16) __half g_hUr [(size_t)MM * HH];
__device__ __align__(16) __half g_zlin[(size_t)MM * HH];
__device__ int g_vid[MM];
__device__ __align__(16) float g_emb3[(size_t)VV * 768];
__device__ __align__(16) us g_embhi[VV * 256];
__device__ __align__(16) us g_emblo[VV * 256];
__device__ __align__(16) us g_Wprehi[768 * 256];
__device__ __align__(16) us g_Wprelo[768 * 256];
__device__ __align__(16) us g_Wz2hi[256 * 256];
__device__ __align__(16) us g_Wz2lo[256 * 256];
__device__ __align__(16) us g_Wh2hi[256 * 256];
__device__ __align__(16) us g_Wh2lo[256 * 256];
__device__ __align__(16) us g_Urhi[256 * 256];
__device__ __align__(16) us g_Urlo[256 * 256];

__device__ __forceinline__ float sigmf(float v) { return 1.0f / (1.0f + expf(-v)); }
__device__ __forceinline__ void split_bf(float v, us& hi, us& lo) {
    __nv_bfloat16 h = __float2bfloat16(v);
    __nv_bfloat16 l = __float2bfloat16(v - __bfloat162float(h));
    hi = *(us*)&h; lo = *(us*)&l;
}
__device__ __forceinline__ float join_bf(us hi, us lo) {
    return __bfloat162float(*(__nv_bfloat16*)&hi) + __bfloat162float(*(__nv_bfloat16*)&lo);
}
struct us2 { us x, y; };
struct us4 { us x, y, z, w; };

__device__ __forceinline__ uint32_t smem_u32(const void* p) {
    uint32_t a;
    asm("{ .reg .u64 t; cvta.to.shared.u64 t, %1; cvt.u32.u64 %0, t; }" : "=r"(a) : "l"(p));
    return a;
}
__device__ __forceinline__ void ldsm4(uint32_t* r, uint32_t addr) {
    asm volatile("ldmatrix.sync.aligned.m8n8.x4.shared.b16 {%0,%1,%2,%3}, [%4];"
        : "=r"(r[0]), "=r"(r[1]), "=r"(r[2]), "=r"(r[3]) : "r"(addr));
}
__device__ __forceinline__ void mma16816(float* d, const uint32_t* a, const uint32_t* b) {
    asm volatile("mma.sync.aligned.m16n8k16.row.col.f32.bf16.bf16.f32 "
        "{%0,%1,%2,%3}, {%4,%5,%6,%7}, {%8,%9}, {%0,%1,%2,%3};"
        : "+f"(d[0]), "+f"(d[1]), "+f"(d[2]), "+f"(d[3])
        : "r"(a[0]), "r"(a[1]), "r"(a[2]), "r"(a[3]), "r"(b[0]), "r"(b[1]));
}

// ---------------------------------------------------------------------------
// weight pack + split
// ---------------------------------------------------------------------------
__global__ void k_pack(const float* __restrict__ Wz, const float* __restrict__ Wr,
                       const float* __restrict__ Wh, const float* __restrict__ Ur) {
    int idx = blockIdx.x * blockDim.x + threadIdx.x;
    int j = idx >> 8, i = idx & 255;
    float v; us hi, lo;
    if (j < 256)       v = Wz[j * 512 + i];
    else if (j < 512)  v = Wr[(j - 256) * 256 + i];
    else if (j < 768)  v = Wh[(j - 512) * 512 + i];
    else if (j < 1024) v = Wz[(j - 768) * 512 + 256 + i];
    else if (j < 1280) v = Wh[(j - 1024) * 512 + 256 + i];
    else               v = Ur[(j - 1280) * 256 + i];
    split_bf(v, hi, lo);
    if (j < 768)        { g_Wprehi[j * 256 + i] = hi;          g_Wprelo[j * 256 + i] = lo; }
    else if (j < 1024)  { g_Wz2hi[(j - 768) * 256 + i] = hi;   g_Wz2lo[(j - 768) * 256 + i] = lo; }
    else if (j < 1280)  { g_Wh2hi[(j - 1024) * 256 + i] = hi;  g_Wh2lo[(j - 1024) * 256 + i] = lo; }
    else                { g_Urhi[(j - 1280) * 256 + i] = hi;   g_Urlo[(j - 1280) * 256 + i] = lo; }
}

__global__ void k_packemb(const float* __restrict__ emb) {
    int idx = blockIdx.x * blockDim.x + threadIdx.x;
    if (idx >= VV * 256) return;
    us hi, lo;
    split_bf(emb[idx], hi, lo);
    g_embhi[idx] = hi; g_emblo[idx] = lo;
}

__global__ void k_vid(const int* __restrict__ fnode, const int* __restrict__ fmess) {
    int m = blockIdx.x * blockDim.x + threadIdx.x;
    if (m < MM) g_vid[m] = fnode[fmess[m]];
}

// ===========================================================================
// split-bf16 mma.sync GEMM (R4 core): CTA 128x128, 8 warps, warp tile 32x64,
// k-chunk 32, 2-stage cp.async, rows stride 80B.
// ===========================================================================
#define STG 40960
#define SMEM_GEMM (2 * STG)
#define STG1 20480
#define SMEM_GEMM1 (2 * STG1)

__device__ __forceinline__ void issue_stage(
    uint32_t sb, const us* __restrict__ Ahi, const us* __restrict__ Alo,
    const us* __restrict__ Bhi, const us* __restrict__ Blo,
    int bm, int bn, int kc, int Mrows)
{
    int tid = threadIdx.x;
#pragma unroll
    for (int i = 0; i < 4; i++) {           // A planes
        int v = tid + i * 256;
        int plane = v >> 9, w = v & 511;
        int rr = w >> 2, cc = w & 3;
        int row = bm + rr;
        int sz = (row < Mrows) ? 16 : 0;
        const us* src = (plane ? Alo : Ahi) +
            (size_t)(row < Mrows ? row : 0) * 256 + kc + cc * 8;
        uint32_t dst = sb + plane * 10240 + rr * 80 + cc * 16;
        asm volatile("cp.async.cg.shared.global [%0], [%1], 16, %2;"
                     :: "r"(dst), "l"(src), "r"(sz));
    }
#pragma unroll
    for (int i = 0; i < 4; i++) {           // B planes
        int v = tid + i * 256;
        int plane = v >> 9, w = v & 511;
        int rr = w >> 2, cc = w & 3;
        const us* src = (plane ? Blo : Bhi) + (size_t)(bn + rr) * 256 + kc + cc * 8;
        uint32_t dst = sb + 20480 + plane * 10240 + rr * 80 + cc * 16;
        asm volatile("cp.async.cg.shared.global [%0], [%1], 16, %2;"
                     :: "r"(dst), "l"(src), "r"(16));
    }
    asm volatile("cp.async.commit_group;" ::: "memory");
}

__device__ __forceinline__ void compute_stage(uint32_t sb, int warp_m, int warp_n,
                                              int lane, float acc[2][8][4]) {
    int quad = lane >> 3, lr = lane & 7;
    int rowA = ((quad & 1) << 3) + lr;
    int colA = (quad & 2) ? 8 : 0;
    int rowB = ((quad >> 1) << 3) + lr;
    int colB = (quad & 1) ? 8 : 0;
#pragma unroll
    for (int step = 0; step < 2; step++) {
        int kb = step * 16;
        uint32_t ahi[2][4], alo[2][4], bhi[8][2], blo[8][2];
#pragma unroll
        for (int mt = 0; mt < 2; mt++) {
            uint32_t ah = sb + (warp_m * 32 + mt * 16 + rowA) * 80 + (kb + colA) * 2;
            ldsm4(ahi[mt], ah);
            ldsm4(alo[mt], ah + 10240);
        }
#pragma unroll
        for (int np = 0; np < 4; np++) {
            uint32_t bh = sb + 20480 + (warp_n * 64 + np * 16 + rowB) * 80 + (kb + colB) * 2;
            uint32_t r[4];
            ldsm4(r, bh);
            bhi[np * 2][0] = r[0]; bhi[np * 2][1] = r[1];
            bhi[np * 2 + 1][0] = r[2]; bhi[np * 2 + 1][1] = r[3];
            ldsm4(r, bh + 10240);
            blo[np * 2][0] = r[0]; blo[np * 2][1] = r[1];
            blo[np * 2 + 1][0] = r[2]; blo[np * 2 + 1][1] = r[3];
        }
#pragma unroll
        for (int mt = 0; mt < 2; mt++)
#pragma unroll
            for (int nt = 0; nt < 8; nt++) {
                mma16816(acc[mt][nt], ahi[mt], bhi[nt]);
                mma16816(acc[mt][nt], alo[mt], bhi[nt]);
                mma16816(acc[mt][nt], ahi[mt], blo[nt]);
            }
    }
}

__device__ __forceinline__ void gemm_main(
    char* smc, const us* Ahi, const us* Alo,
    const us* Whi, const us* Wlo,
    int bm, int bn, int Mrows, float acc[2][8][4])
{
#pragma unroll
    for (int a = 0; a < 2; a++)
#pragma unroll
        for (int b = 0; b < 8; b++)
#pragma unroll
            for (int c = 0; c < 4; c++) acc[a][b][c] = 0.0f;

    uint32_t sb = smem_u32(smc);
    int lane = threadIdx.x & 31, wid = threadIdx.x >> 5;
    int warp_m = wid & 3, warp_n = wid >> 2;

    issue_stage(sb, Ahi, Alo, Whi, Wlo, bm, bn, 0, Mrows);
    for (int s = 0; s < 8; s++) {
        if (s < 7) {
            issue_stage(sb + ((s + 1) & 1) * STG, Ahi, Alo, Whi, Wlo, bm, bn, (s + 1) * 32, Mrows);
            asm volatile("cp.async.wait_group 1;" ::: "memory");
        } else {
            asm volatile("cp.async.wait_group 0;" ::: "memory");
        }
        __syncthreads();
        compute_stage(sb + (s & 1) * STG, warp_m, warp_n, lane, acc);
        __syncthreads();
    }
}

// ---------------- 1-term (hi x hi) GEMM variant for the r-gate ---------------
__device__ __forceinline__ void issue_stage1(
    uint32_t sb, const us* __restrict__ Ahi, const us* __restrict__ Bhi,
    int bm, int bn, int kc)
{
    int tid = threadIdx.x;
#pragma unroll
    for (int i = 0; i < 2; i++) {           // A hi plane
        int v = tid + i * 256;
        int rr = v >> 2, cc = v & 3;
        int row = bm + rr;
        int sz = (row < MM) ? 16 : 0;
        const us* src = Ahi + (size_t)(row < MM ? row : 0) * 256 + kc + cc * 8;
        uint32_t dst = sb + rr * 80 + cc * 16;
        asm volatile("cp.async.cg.shared.global [%0], [%1], 16, %2;"
                     :: "r"(dst), "l"(src), "r"(sz));
    }
#pragma unroll
    for (int i = 0; i < 2; i++) {           // B hi plane
        int v = tid + i * 256;
        int rr = v >> 2, cc = v & 3;
        const us* src = Bhi + (size_t)(bn + rr) * 256 + kc + cc * 8;
        uint32_t dst = sb + 10240 + rr * 80 + cc * 16;
        asm volatile("cp.async.cg.shared.global [%0], [%1], 16, %2;"
                     :: "r"(dst), "l"(src), "r"(16));
    }
    asm volatile("cp.async.commit_group;" ::: "memory");
}

__device__ __forceinline__ void compute_stage1(uint32_t sb, int warp_m, int warp_n,
                                               int lane, float acc[2][8][4]) {
    int quad = lane >> 3, lr = lane & 7;
    int rowA = ((quad & 1) << 3) + lr;
    int colA = (quad & 2) ? 8 : 0;
    int rowB = ((quad >> 1) << 3) + lr;
    int colB = (quad & 1) ? 8 : 0;
#pragma unroll
    for (int step = 0; step < 2; step++) {
        int kb = step * 16;
        uint32_t ahi[2][4], bhi[8][2];
#pragma unroll
        for (int mt = 0; mt < 2; mt++)
            ldsm4(ahi[mt], sb + (warp_m * 32 + mt * 16 + rowA) * 80 + (kb + colA) * 2);
#pragma unroll
        for (int np = 0; np < 4; np++) {
            uint32_t r[4];
            ldsm4(r, sb + 10240 + (warp_n * 64 + np * 16 + rowB) * 80 + (kb + colB) * 2);
            bhi[np * 2][0] = r[0]; bhi[np * 2][1] = r[1];
            bhi[np * 2 + 1][0] = r[2]; bhi[np * 2 + 1][1] = r[3];
        }
#pragma unroll
        for (int mt = 0; mt < 2; mt++)
#pragma unroll
            for (int nt = 0; nt < 8; nt++)
                mma16816(acc[mt][nt], ahi[mt], bhi[nt]);
    }
}

__global__ __launch_bounds__(256)
void k_gemm1_h(const us* __restrict__ Ahi, const us* __restrict__ Whi,
               __half* __restrict__ C, int ldc) {
    extern __shared__ char smc[];
    uint32_t sb = smem_u32(smc);
    int bm = blockIdx.x * 128, bn = blockIdx.y * 128;
    int lane = threadIdx.x & 31, wid = threadIdx.x >> 5;
    int warp_m = wid & 3, warp_n = wid >> 2;
    float acc[2][8][4];
#pragma unroll
    for (int a = 0; a < 2; a++)
#pragma unroll
        for (int b = 0; b < 8; b++)
#pragma unroll
            for (int c = 0; c < 4; c++) acc[a][b][c] = 0.0f;

    issue_stage1(sb, Ahi, Whi, bm, bn, 0);
    for (int s = 0; s < 8; s++) {
        if (s < 7) {
            issue_stage1(sb + ((s + 1) & 1) * STG1, Ahi, Whi, bm, bn, (s + 1) * 32);
            asm volatile("cp.async.wait_group 1;" ::: "memory");
        } else {
            asm volatile("cp.async.wait_group 0;" ::: "memory");
        }
        __syncthreads();
        compute_stage1(sb + (s & 1) * STG1, warp_m, warp_n, lane, acc);
        __syncthreads();
    }

    int g = lane >> 2, tig = lane & 3;
#pragma unroll
    for (int mt = 0; mt < 2; mt++) {
        int row0 = bm + warp_m * 32 + mt * 16 + g;
#pragma unroll
        for (int nt = 0; nt < 8; nt++) {
            int col = bn + warp_n * 64 + nt * 8 + tig * 2;
            if (row0 < MM)
                *(__half2*)(C + (size_t)row0 * ldc + col) =
                    __floats2half2_rn(acc[mt][nt][0], acc[mt][nt][1]);
            if (row0 + 8 < MM)
                *(__half2*)(C + (size_t)(row0 + 8) * ldc + col) =
                    __floats2half2_rn(acc[mt][nt][2], acc[mt][nt][3]);
        }
    }
}

// ---------------- 3-term GEMM with fp16 output --------------------------------
__global__ __launch_bounds__(256)
void k_gemm_h(const us* __restrict__ Ahi, const us* __restrict__ Alo,
              const us* __restrict__ Whi, const us* __restrict__ Wlo,
              __half* __restrict__ C, int Mrows, int ldc) {
    extern __shared__ char smc[];
    int bm = blockIdx.x * 128, bn = blockIdx.y * 128;
    float acc[2][8][4];
    gemm_main(smc, Ahi, Alo, Whi, Wlo, bm, bn, Mrows, acc);
    int lane = threadIdx.x & 31, wid = threadIdx.x >> 5;
    int g = lane >> 2, tig = lane & 3;
#pragma unroll
    for (int mt = 0; mt < 2; mt++) {
        int row0 = bm + (wid & 3) * 32 + mt * 16 + g;
#pragma unroll
        for (int nt = 0; nt < 8; nt++) {
            int col = bn + (wid >> 2) * 64 + nt * 8 + tig * 2;
            if (row0 < Mrows)
                *(__half2*)(C + (size_t)row0 * ldc + col) =
                    __floats2half2_rn(acc[mt][nt][0], acc[mt][nt][1]);
            if (row0 + 8 < Mrows)
                *(__half2*)(C + (size_t)(row0 + 8) * ldc + col) =
                    __floats2half2_rn(acc[mt][nt][2], acc[mt][nt][3]);
        }
    }
}

// ---------------- 3-term GEMM with fp32 output (emb3) ------------------------
__global__ __launch_bounds__(256)
void k_gemm_f(const us* __restrict__ Ahi, const us* __restrict__ Alo,
              const us* __restrict__ Whi, const us* __restrict__ Wlo,
              float* __restrict__ C, int Mrows, int ldc) {
    extern __shared__ char smc[];
    int bm = blockIdx.x * 128, bn = blockIdx.y * 128;
    float acc[2][8][4];
    gemm_main(smc, Ahi, Alo, Whi, Wlo, bm, bn, Mrows, acc);
    int lane = threadIdx.x & 31, wid = threadIdx.x >> 5;
    int g = lane >> 2, tig = lane & 3;
#pragma unroll
    for (int mt = 0; mt < 2; mt++) {
        int row0 = bm + (wid & 3) * 32 + mt * 16 + g;
#pragma unroll
        for (int nt = 0; nt < 8; nt++) {
            int col = bn + (wid >> 2) * 64 + nt * 8 + tig * 2;
            if (row0 < Mrows)
                *(float2*)(C + (size_t)row0 * ldc + col) =
                    make_float2(acc[mt][nt][0], acc[mt][nt][1]);
            if (row0 + 8 < Mrows)
                *(float2*)(C + (size_t)(row0 + 8) * ldc + col) =
                    make_float2(acc[mt][nt][2], acc[mt][nt][3]);
        }
    }
}

// ---------------- GEMM (sumg @ Wh2^T) with fused GRU update ------------------
__device__ __forceinline__ void gru2(int row, int col, float a0, float a1,
                                     const float* __restrict__ bz,
                                     const float* __restrict__ bh,
                                     float* __restrict__ Hout) {
    if (row >= MM) return;
    size_t e768 = (size_t)g_vid[row] * 768 + col;
    size_t o256 = (size_t)row * 256 + col;
    float2 xz = *(const float2*)(g_emb3 + e768);
    float2 xh = *(const float2*)(g_emb3 + e768 + 512);
    float2 zl = __half22float2(*(const __half2*)(g_zlin + o256));
    us2 shh = *(const us2*)(g_shhi + o256);
    us2 shl = *(const us2*)(g_shlo + o256);
    float2 bzv = *(const float2*)(bz + col);
    float2 bhv = *(const float2*)(bh + col);
    float sh0 = join_bf(shh.x, shl.x);
    float sh1 = join_bf(shh.y, shl.y);
    float z0 = sigmf(xz.x + zl.x + bzv.x);
    float p0 = tanhf(xh.x + a0 + bhv.x);
    float o0 = (1.0f - z0) * sh0 + z0 * p0;
    float z1 = sigmf(xz.y + zl.y + bzv.y);
    float p1 = tanhf(xh.y + a1 + bhv.y);
    float o1 = (1.0f - z1) * sh1 + z1 * p1;
    if (row == 0) { o0 = 0.0f; o1 = 0.0f; }
    *(float2*)(Hout + o256) = make_float2(o0, o1);
    us2 hi, lo;
    split_bf(o0, hi.x, lo.x); split_bf(o1, hi.y, lo.y);
    *(us2*)(g_hhi + o256) = hi;
    *(us2*)(g_hlo + o256) = lo;
}

__global__ __launch_bounds__(256)
void k_gemm_gru(const us* __restrict__ Ahi, const us* __restrict__ Alo,
                const us* __restrict__ Whi, const us* __restrict__ Wlo,
                float* __restrict__ Hout, const float* __restrict__ bz,
                const float* __restrict__ bh) {
    extern __shared__ char smc[];
    int bm = blockIdx.x * 128, bn = blockIdx.y * 128;
    float acc[2][8][4];
    gemm_main(smc, Ahi, Alo, Whi, Wlo, bm, bn, MM, acc);
    int lane = threadIdx.x & 31, wid = threadIdx.x >> 5;
    int g = lane >> 2, tig = lane & 3;
#pragma unroll
    for (int mt = 0; mt < 2; mt++) {
        int row0 = bm + (wid & 3) * 32 + mt * 16 + g;
#pragma unroll
        for (int nt = 0; nt < 8; nt++) {
            int col = bn + (wid >> 2) * 64 + nt * 8 + tig * 2;
            gru2(row0, col, acc[mt][nt][0], acc[mt][nt][1], bz, bh, Hout);
            gru2(row0 + 8, col, acc[mt][nt][2], acc[mt][nt][3], bz, bh, Hout);
        }
    }
}

// ---------------------------------------------------------------------------
// first GRU step (h == 0)
// ---------------------------------------------------------------------------
__global__ void k_first(float* __restrict__ h, const float* __restrict__ bz,
                        const float* __restrict__ bh) {
    int e = blockIdx.x * blockDim.x + threadIdx.x;
    if (e >= MM * 64) return;
    int m = e >> 6, c = (e & 63) * 4;
    size_t e768 = (size_t)g_vid[m] * 768 + c;
    float4 xz = *(const float4*)(g_emb3 + e768);
    float4 xh = *(const float4*)(g_emb3 + e768 + 512);
    float4 bzv = *(const float4*)(bz + c);
    float4 bhv = *(const float4*)(bh + c);
    float4 o;
    o.x = sigmf(xz.x + bzv.x) * tanhf(xh.x + bhv.x);
    o.y = sigmf(xz.y + bzv.y) * tanhf(xh.y + bhv.y);
    o.z = sigmf(xz.z + bzv.z) * tanhf(xh.z + bhv.z);
    o.w = sigmf(xz.w + bzv.w) * tanhf(xh.w + bhv.w);
    if (m == 0) o = make_float4(0.f, 0.f, 0.f, 0.f);
    *(float4*)(h + (size_t)m * HH + c) = o;
    us4 hi, lo;
    split_bf(o.x, hi.x, lo.x); split_bf(o.y, hi.y, lo.y);
    split_bf(o.z, hi.z, lo.z); split_bf(o.w, hi.w, lo.w);
    *(us4*)(g_hhi + (size_t)m * HH + c) = hi;
    *(us4*)(g_hlo + (size_t)m * HH + c) = lo;
}

// ---------------------------------------------------------------------------
// gather
// ---------------------------------------------------------------------------
__global__ void k_gather(const float* __restrict__ h, const int* __restrict__ mg,
                         const float* __restrict__ bu) {
    int m = blockIdx.x * blockDim.y + threadIdx.y;
    if (m >= MM) return;
    int c = threadIdx.x * 4;
    int idx[KK];
#pragma unroll
    for (int k = 0; k < KK; k++) idx[k] = mg[m * KK + k];
    float4 xr = *(const float4*)(g_emb3 + (size_t)g_vid[m] * 768 + 256 + c);
    float4 bv = *(const float4*)(bu + c);
    float4 as = make_float4(0.f, 0.f, 0.f, 0.f);
    float4 ag = make_float4(0.f, 0.f, 0.f, 0.f);
#pragma unroll
    for (int k = 0; k < KK; k++) {
        const float4 hv = *(const float4*)(h + (size_t)idx[k] * HH + c);
        const __half2* up = (const __half2*)(g_hUr + (size_t)idx[k] * HH + c);
        float2 u0 = __half22float2(up[0]);
        float2 u1 = __half22float2(up[1]);
        float rx = sigmf(xr.x + u0.x + bv.x);
        float ry = sigmf(xr.y + u0.y + bv.y);
        float rz = sigmf(xr.z + u1.x + bv.z);
        float rw = sigmf(xr.w + u1.y + bv.w);
        as.x += hv.x; as.y += hv.y; as.z += hv.z; as.w += hv.w;
        ag.x = fmaf(rx, hv.x, ag.x); ag.y = fmaf(ry, hv.y, ag.y);
        ag.z = fmaf(rz, hv.z, ag.z); ag.w = fmaf(rw, hv.w, ag.w);
    }
    us4 hi, lo;
    split_bf(as.x, hi.x, lo.x); split_bf(as.y, hi.y, lo.y);
    split_bf(as.z, hi.z, lo.z); split_bf(as.w, hi.w, lo.w);
    *(us4*)(g_shhi + (size_t)m * HH + c) = hi;
    *(us4*)(g_shlo + (size_t)m * HH + c) = lo;
    split_bf(ag.x, hi.x, lo.x); split_bf(ag.y, hi.y, lo.y);
    split_bf(ag.z, hi.z, lo.z); split_bf(ag.w, hi.w, lo.w);
    *(us4*)(g_sghi + (size_t)m * HH + c) = hi;
    *(us4*)(g_sglo + (size_t)m * HH + c) = lo;
}

// ---------------------------------------------------------------------------
// readout (B=64 roots)
// ---------------------------------------------------------------------------
__global__ void k_readout(const int* __restrict__ scope_st, const int* __restrict__ fnode,
                          const int* __restrict__ node_graph, const float* __restrict__ emb,
                          const float* __restrict__ h, const float* __restrict__ Wo,
                          const float* __restrict__ bo, float* __restrict__ out) {
    __shared__ float fe[HH];
    __shared__ float mn[HH];
    int b = blockIdx.x, j = threadIdx.x;
    int n = scope_st[b];
    fe[j] = emb[(size_t)fnode[n] * HH + j];
    float s = 0.0f;
#pragma unroll
    for (int k = 0; k < KK; k++) s += h[(size_t)node_graph[n * KK + k] * HH + j];
    mn[j] = s;
    __syncthreads();
    float acc = bo[j];
    const float* wrow = Wo + (size_t)j * 512;
#pragma unroll 4
    for (int i = 0; i < 256; i += 4) {
        float4 w = *(const float4*)(wrow + i);
        float4 f = *(const float4*)&fe[i];
        acc = fmaf(w.x, f.x, acc); acc = fmaf(w.y, f.y, acc);
        acc = fmaf(w.z, f.z, acc); acc = fmaf(w.w, f.w, acc);
    }
#pragma unroll 4
    for (int i = 0; i < 256; i += 4) {
        float4 w = *(const float4*)(wrow + 256 + i);
        float4 f = *(const float4*)&mn[i];
        acc = fmaf(w.x, f.x, acc); acc = fmaf(w.y, f.y, acc);
        acc = fmaf(w.z, f.z, acc); acc = fmaf(w.w, f.w, acc);
    }
    out[(size_t)b * HH + j] = fmaxf(acc, 0.0f);
}

// ---------------------------------------------------------------------------
// launch
// ---------------------------------------------------------------------------
extern "C" void kernel_launch(void* const* d_in, const int* in_sizes, int n_in,
                              void* d_out, int out_size) {
    const int*   fnode      = (const int*)  d_in[0];
    const int*   fmess      = (const int*)  d_in[1];
    const int*   node_graph = (const int*)  d_in[2];
    const int*   mess_graph = (const int*)  d_in[3];
    const int*   scope_st   = (const int*)  d_in[4];
    const float* emb        = (const float*)d_in[5];
    const float* Wz         = (const float*)d_in[6];
    const float* bz         = (const float*)d_in[7];
    const float* Wr         = (const float*)d_in[8];
    const float* Ur         = (const float*)d_in[9];
    const float* bu         = (const float*)d_in[10];
    const float* Wh         = (const float*)d_in[11];
    const float* bh         = (const float*)d_in[12];
    const float* Wo         = (const float*)d_in[13];
    const float* bo         = (const float*)d_in[14];

    float* out = (float*)d_out;
    float* h = out + (size_t)BB * HH;

    cudaFuncSetAttribute(k_gemm_h,   cudaFuncAttributeMaxDynamicSharedMemorySize, SMEM_GEMM);
    cudaFuncSetAttribute(k_gemm_f,   cudaFuncAttributeMaxDynamicSharedMemorySize, SMEM_GEMM);
    cudaFuncSetAttribute(k_gemm_gru, cudaFuncAttributeMaxDynamicSharedMemorySize, SMEM_GEMM);
    cudaFuncSetAttribute(k_gemm1_h,  cudaFuncAttributeMaxDynamicSharedMemorySize, SMEM_GEMM1);

    us *hhi, *hlo, *shhi, *shlo, *sghi, *sglo, *embhi, *emblo;
    us *Wprehi, *Wprelo, *Wz2hi, *Wz2lo, *Wh2hi, *Wh2lo, *Urhi, *Urlo;
    __half *hUrp, *zlinp; float *emb3p;
    cudaGetSymbolAddress((void**)&hhi, g_hhi);   cudaGetSymbolAddress((void**)&hlo, g_hlo);
    cudaGetSymbolAddress((void**)&shhi, g_shhi); cudaGetSymbolAddress((void**)&shlo, g_shlo);
    cudaGetSymbolAddress((void**)&sghi, g_sghi); cudaGetSymbolAddress((void**)&sglo, g_sglo);
    cudaGetSymbolAddress((void**)&embhi, g_embhi); cudaGetSymbolAddress((void**)&emblo, g_emblo);
    cudaGetSymbolAddress((void**)&Wprehi, g_Wprehi); cudaGetSymbolAddress((void**)&Wprelo, g_Wprelo);
    cudaGetSymbolAddress((void**)&Wz2hi, g_Wz2hi);   cudaGetSymbolAddress((void**)&Wz2lo, g_Wz2lo);
    cudaGetSymbolAddress((void**)&Wh2hi, g_Wh2hi);   cudaGetSymbolAddress((void**)&Wh2lo, g_Wh2lo);
    cudaGetSymbolAddress((void**)&Urhi, g_Urhi);     cudaGetSymbolAddress((void**)&Urlo, g_Urlo);
    cudaGetSymbolAddress((void**)&emb3p, g_emb3);
    cudaGetSymbolAddress((void**)&zlinp, g_zlin);
    cudaGetSymbolAddress((void**)&hUrp, g_hUr);

    const int ETH = 256;
    const int EBL = (MM * 64 + ETH - 1) / ETH;
    const int MT  = (MM + 127) / 128;
    const int VT  = (VV + 127) / 128;

    k_pack   <<<1536, 256>>>(Wz, Wr, Wh, Ur);
    k_packemb<<<(VV * 256 + 255) / 256, 256>>>(emb);
    k_vid    <<<(MM + 255) / 256, 256>>>(fnode, fmess);

    k_gemm_f<<<dim3(VT, 6), 256, SMEM_GEMM>>>(embhi, emblo, Wprehi, Wprelo, emb3p, VV, 768);
    k_first<<<EBL, ETH>>>(h, bz, bh);

    for (int it = 1; it < NDEPTH; it++) {
        k_gemm1_h<<<dim3(MT, 2), 256, SMEM_GEMM1>>>(hhi, Urhi, hUrp, 256);   // r-gate: 1-term
        k_gather<<<(MM + 3) / 4, dim3(64, 4)>>>(h, mess_graph, bu);
        k_gemm_h<<<dim3(MT, 2), 256, SMEM_GEMM>>>(shhi, shlo, Wz2hi, Wz2lo, zlinp, MM, 256);
        k_gemm_gru<<<dim3(MT, 2), 256, SMEM_GEMM>>>(sghi, sglo, Wh2hi, Wh2lo, h, bz, bh);
    }

    k_readout<<<BB, HH>>>(scope_st, fnode, node_graph, emb, h, Wo, bo, out);
}

// round 17
// speedup vs baseline: 1.8168x; 1.0680x over previous
#include <cuda_runtime.h>
#include <cuda_bf16.h>
#include <cuda_fp16.h>
#include <math.h>
#include <stdint.h>

#define MM 100001
#define NN 50000
#define VV 780
#define HH 256
#define KK 6
#define BB 64
#define NDEPTH 6

typedef unsigned short us;

// ---------------------------------------------------------------------------
// scratch
// ---------------------------------------------------------------------------
__device__ __align__(16) us g_hhi[(size_t)MM * HH];
__device__ __align__(16) us g_hlo[(size_t)MM * HH];
__device__ __align__(16) us g_shhi[(size_t)MM * HH];
__device__ __align__(16) us g_shlo[(size_t)MM * HH];
__device__ __align__(16) us g_sghi[(size_t)MM * HH];
__device__ __align__(16) us g_sglo[(size_t)MM * HH];
__device__ __align__(16) __half g_hUr [(size_t)MM * HH];
__device__ __align__(16) __half g_zlin[(size_t)MM * HH];
__device__ int g_vid[MM];
__device__ __align__(16) float g_emb3[(size_t)VV * 768];
__device__ __align__(16) us g_embhi[VV * 256];
__device__ __align__(16) us g_emblo[VV * 256];
__device__ __align__(16) us g_Wprehi[768 * 256];
__device__ __align__(16) us g_Wprelo[768 * 256];
__device__ __align__(16) us g_Wz2hi[256 * 256];
__device__ __align__(16) us g_Wz2lo[256 * 256];
__device__ __align__(16) us g_Wh2hi[256 * 256];
__device__ __align__(16) us g_Wh2lo[256 * 256];
__device__ __align__(16) us g_Urhi[256 * 256];
__device__ __align__(16) us g_Urlo[256 * 256];

__device__ __forceinline__ float sigmf(float v) { return 1.0f / (1.0f + expf(-v)); }
__device__ __forceinline__ void split_bf(float v, us& hi, us& lo) {
    __nv_bfloat16 h = __float2bfloat16(v);
    __nv_bfloat16 l = __float2bfloat16(v - __bfloat162float(h));
    hi = *(us*)&h; lo = *(us*)&l;
}
__device__ __forceinline__ float join_bf(us hi, us lo) {
    return __bfloat162float(*(__nv_bfloat16*)&hi) + __bfloat162float(*(__nv_bfloat16*)&lo);
}
struct us2 { us x, y; };
struct us4 { us x, y, z, w; };

__device__ __forceinline__ uint32_t smem_u32(const void* p) {
    uint32_t a;
    asm("{ .reg .u64 t; cvta.to.shared.u64 t, %1; cvt.u32.u64 %0, t; }" : "=r"(a) : "l"(p));
    return a;
}
__device__ __forceinline__ void ldsm4(uint32_t* r, uint32_t addr) {
    asm volatile("ldmatrix.sync.aligned.m8n8.x4.shared.b16 {%0,%1,%2,%3}, [%4];"
        : "=r"(r[0]), "=r"(r[1]), "=r"(r[2]), "=r"(r[3]) : "r"(addr));
}
__device__ __forceinline__ void mma16816(float* d, const uint32_t* a, const uint32_t* b) {
    asm volatile("mma.sync.aligned.m16n8k16.row.col.f32.bf16.bf16.f32 "
        "{%0,%1,%2,%3}, {%4,%5,%6,%7}, {%8,%9}, {%0,%1,%2,%3};"
        : "+f"(d[0]), "+f"(d[1]), "+f"(d[2]), "+f"(d[3])
        : "r"(a[0]), "r"(a[1]), "r"(a[2]), "r"(a[3]), "r"(b[0]), "r"(b[1]));
}

// ---------------------------------------------------------------------------
// weight pack + split
// ---------------------------------------------------------------------------
__global__ void k_pack(const float* __restrict__ Wz, const float* __restrict__ Wr,
                       const float* __restrict__ Wh, const float* __restrict__ Ur) {
    int idx = blockIdx.x * blockDim.x + threadIdx.x;
    int j = idx >> 8, i = idx & 255;
    float v; us hi, lo;
    if (j < 256)       v = Wz[j * 512 + i];
    else if (j < 512)  v = Wr[(j - 256) * 256 + i];
    else if (j < 768)  v = Wh[(j - 512) * 512 + i];
    else if (j < 1024) v = Wz[(j - 768) * 512 + 256 + i];
    else if (j < 1280) v = Wh[(j - 1024) * 512 + 256 + i];
    else               v = Ur[(j - 1280) * 256 + i];
    split_bf(v, hi, lo);
    if (j < 768)        { g_Wprehi[j * 256 + i] = hi;          g_Wprelo[j * 256 + i] = lo; }
    else if (j < 1024)  { g_Wz2hi[(j - 768) * 256 + i] = hi;   g_Wz2lo[(j - 768) * 256 + i] = lo; }
    else if (j < 1280)  { g_Wh2hi[(j - 1024) * 256 + i] = hi;  g_Wh2lo[(j - 1024) * 256 + i] = lo; }
    else                { g_Urhi[(j - 1280) * 256 + i] = hi;   g_Urlo[(j - 1280) * 256 + i] = lo; }
}

__global__ void k_packemb(const float* __restrict__ emb) {
    int idx = blockIdx.x * blockDim.x + threadIdx.x;
    if (idx >= VV * 256) return;
    us hi, lo;
    split_bf(emb[idx], hi, lo);
    g_embhi[idx] = hi; g_emblo[idx] = lo;
}

__global__ void k_vid(const int* __restrict__ fnode, const int* __restrict__ fmess) {
    int m = blockIdx.x * blockDim.x + threadIdx.x;
    if (m < MM) g_vid[m] = fnode[fmess[m]];
}

// ===========================================================================
// split-bf16 mma.sync GEMM (R4 core): CTA 128x128, 8 warps, warp tile 32x64,
// k-chunk 32, 2-stage cp.async, rows stride 80B.
// ===========================================================================
#define STG 40960
#define SMEM_GEMM (2 * STG)
#define STG1 20480
#define SMEM_GEMM1 (2 * STG1)

__device__ __forceinline__ void issue_stage(
    uint32_t sb, const us* __restrict__ Ahi, const us* __restrict__ Alo,
    const us* __restrict__ Bhi, const us* __restrict__ Blo,
    int bm, int bn, int kc, int Mrows)
{
    int tid = threadIdx.x;
#pragma unroll
    for (int i = 0; i < 4; i++) {           // A planes
        int v = tid + i * 256;
        int plane = v >> 9, w = v & 511;
        int rr = w >> 2, cc = w & 3;
        int row = bm + rr;
        int sz = (row < Mrows) ? 16 : 0;
        const us* src = (plane ? Alo : Ahi) +
            (size_t)(row < Mrows ? row : 0) * 256 + kc + cc * 8;
        uint32_t dst = sb + plane * 10240 + rr * 80 + cc * 16;
        asm volatile("cp.async.cg.shared.global [%0], [%1], 16, %2;"
                     :: "r"(dst), "l"(src), "r"(sz));
    }
#pragma unroll
    for (int i = 0; i < 4; i++) {           // B planes
        int v = tid + i * 256;
        int plane = v >> 9, w = v & 511;
        int rr = w >> 2, cc = w & 3;
        const us* src = (plane ? Blo : Bhi) + (size_t)(bn + rr) * 256 + kc + cc * 8;
        uint32_t dst = sb + 20480 + plane * 10240 + rr * 80 + cc * 16;
        asm volatile("cp.async.cg.shared.global [%0], [%1], 16, %2;"
                     :: "r"(dst), "l"(src), "r"(16));
    }
    asm volatile("cp.async.commit_group;" ::: "memory");
}

__device__ __forceinline__ void compute_stage(uint32_t sb, int warp_m, int warp_n,
                                              int lane, float acc[2][8][4]) {
    int quad = lane >> 3, lr = lane & 7;
    int rowA = ((quad & 1) << 3) + lr;
    int colA = (quad & 2) ? 8 : 0;
    int rowB = ((quad >> 1) << 3) + lr;
    int colB = (quad & 1) ? 8 : 0;
#pragma unroll
    for (int step = 0; step < 2; step++) {
        int kb = step * 16;
        uint32_t ahi[2][4], alo[2][4], bhi[8][2], blo[8][2];
#pragma unroll
        for (int mt = 0; mt < 2; mt++) {
            uint32_t ah = sb + (warp_m * 32 + mt * 16 + rowA) * 80 + (kb + colA) * 2;
            ldsm4(ahi[mt], ah);
            ldsm4(alo[mt], ah + 10240);
        }
#pragma unroll
        for (int np = 0; np < 4; np++) {
            uint32_t bh = sb + 20480 + (warp_n * 64 + np * 16 + rowB) * 80 + (kb + colB) * 2;
            uint32_t r[4];
            ldsm4(r, bh);
            bhi[np * 2][0] = r[0]; bhi[np * 2][1] = r[1];
            bhi[np * 2 + 1][0] = r[2]; bhi[np * 2 + 1][1] = r[3];
            ldsm4(r, bh + 10240);
            blo[np * 2][0] = r[0]; blo[np * 2][1] = r[1];
            blo[np * 2 + 1][0] = r[2]; blo[np * 2 + 1][1] = r[3];
        }
#pragma unroll
        for (int mt = 0; mt < 2; mt++)
#pragma unroll
            for (int nt = 0; nt < 8; nt++) {
                mma16816(acc[mt][nt], ahi[mt], bhi[nt]);
                mma16816(acc[mt][nt], alo[mt], bhi[nt]);
                mma16816(acc[mt][nt], ahi[mt], blo[nt]);
            }
    }
}

__device__ __forceinline__ void gemm_main(
    char* smc, const us* Ahi, const us* Alo,
    const us* Whi, const us* Wlo,
    int bm, int bn, int Mrows, float acc[2][8][4])
{
#pragma unroll
    for (int a = 0; a < 2; a++)
#pragma unroll
        for (int b = 0; b < 8; b++)
#pragma unroll
            for (int c = 0; c < 4; c++) acc[a][b][c] = 0.0f;

    uint32_t sb = smem_u32(smc);
    int lane = threadIdx.x & 31, wid = threadIdx.x >> 5;
    int warp_m = wid & 3, warp_n = wid >> 2;

    issue_stage(sb, Ahi, Alo, Whi, Wlo, bm, bn, 0, Mrows);
    for (int s = 0; s < 8; s++) {
        if (s < 7) {
            issue_stage(sb + ((s + 1) & 1) * STG, Ahi, Alo, Whi, Wlo, bm, bn, (s + 1) * 32, Mrows);
            asm volatile("cp.async.wait_group 1;" ::: "memory");
        } else {
            asm volatile("cp.async.wait_group 0;" ::: "memory");
        }
        __syncthreads();
        compute_stage(sb + (s & 1) * STG, warp_m, warp_n, lane, acc);
        __syncthreads();
    }
}

// ---------------- 1-term (hi x hi) GEMM variant for gate paths ---------------
__device__ __forceinline__ void issue_stage1(
    uint32_t sb, const us* __restrict__ Ahi, const us* __restrict__ Bhi,
    int bm, int bn, int kc)
{
    int tid = threadIdx.x;
#pragma unroll
    for (int i = 0; i < 2; i++) {           // A hi plane
        int v = tid + i * 256;
        int rr = v >> 2, cc = v & 3;
        int row = bm + rr;
        int sz = (row < MM) ? 16 : 0;
        const us* src = Ahi + (size_t)(row < MM ? row : 0) * 256 + kc + cc * 8;
        uint32_t dst = sb + rr * 80 + cc * 16;
        asm volatile("cp.async.cg.shared.global [%0], [%1], 16, %2;"
                     :: "r"(dst), "l"(src), "r"(sz));
    }
#pragma unroll
    for (int i = 0; i < 2; i++) {           // B hi plane
        int v = tid + i * 256;
        int rr = v >> 2, cc = v & 3;
        const us* src = Bhi + (size_t)(bn + rr) * 256 + kc + cc * 8;
        uint32_t dst = sb + 10240 + rr * 80 + cc * 16;
        asm volatile("cp.async.cg.shared.global [%0], [%1], 16, %2;"
                     :: "r"(dst), "l"(src), "r"(16));
    }
    asm volatile("cp.async.commit_group;" ::: "memory");
}

__device__ __forceinline__ void compute_stage1(uint32_t sb, int warp_m, int warp_n,
                                               int lane, float acc[2][8][4]) {
    int quad = lane >> 3, lr = lane & 7;
    int rowA = ((quad & 1) << 3) + lr;
    int colA = (quad & 2) ? 8 : 0;
    int rowB = ((quad >> 1) << 3) + lr;
    int colB = (quad & 1) ? 8 : 0;
#pragma unroll
    for (int step = 0; step < 2; step++) {
        int kb = step * 16;
        uint32_t ahi[2][4], bhi[8][2];
#pragma unroll
        for (int mt = 0; mt < 2; mt++)
            ldsm4(ahi[mt], sb + (warp_m * 32 + mt * 16 + rowA) * 80 + (kb + colA) * 2);
#pragma unroll
        for (int np = 0; np < 4; np++) {
            uint32_t r[4];
            ldsm4(r, sb + 10240 + (warp_n * 64 + np * 16 + rowB) * 80 + (kb + colB) * 2);
            bhi[np * 2][0] = r[0]; bhi[np * 2][1] = r[1];
            bhi[np * 2 + 1][0] = r[2]; bhi[np * 2 + 1][1] = r[3];
        }
#pragma unroll
        for (int mt = 0; mt < 2; mt++)
#pragma unroll
            for (int nt = 0; nt < 8; nt++)
                mma16816(acc[mt][nt], ahi[mt], bhi[nt]);
    }
}

__global__ __launch_bounds__(256)
void k_gemm1_h(const us* __restrict__ Ahi, const us* __restrict__ Whi,
               __half* __restrict__ C, int ldc) {
    extern __shared__ char smc[];
    uint32_t sb = smem_u32(smc);
    int bm = blockIdx.x * 128, bn = blockIdx.y * 128;
    int lane = threadIdx.x & 31, wid = threadIdx.x >> 5;
    int warp_m = wid & 3, warp_n = wid >> 2;
    float acc[2][8][4];
#pragma unroll
    for (int a = 0; a < 2; a++)
#pragma unroll
        for (int b = 0; b < 8; b++)
#pragma unroll
            for (int c = 0; c < 4; c++) acc[a][b][c] = 0.0f;

    issue_stage1(sb, Ahi, Whi, bm, bn, 0);
    for (int s = 0; s < 8; s++) {
        if (s < 7) {
            issue_stage1(sb + ((s + 1) & 1) * STG1, Ahi, Whi, bm, bn, (s + 1) * 32);
            asm volatile("cp.async.wait_group 1;" ::: "memory");
        } else {
            asm volatile("cp.async.wait_group 0;" ::: "memory");
        }
        __syncthreads();
        compute_stage1(sb + (s & 1) * STG1, warp_m, warp_n, lane, acc);
        __syncthreads();
    }

    int g = lane >> 2, tig = lane & 3;
#pragma unroll
    for (int mt = 0; mt < 2; mt++) {
        int row0 = bm + warp_m * 32 + mt * 16 + g;
#pragma unroll
        for (int nt = 0; nt < 8; nt++) {
            int col = bn + warp_n * 64 + nt * 8 + tig * 2;
            if (row0 < MM)
                *(__half2*)(C + (size_t)row0 * ldc + col) =
                    __floats2half2_rn(acc[mt][nt][0], acc[mt][nt][1]);
            if (row0 + 8 < MM)
                *(__half2*)(C + (size_t)(row0 + 8) * ldc + col) =
                    __floats2half2_rn(acc[mt][nt][2], acc[mt][nt][3]);
        }
    }
}

// ---------------- 3-term GEMM with fp32 output (emb3) ------------------------
__global__ __launch_bounds__(256)
void k_gemm_f(const us* __restrict__ Ahi, const us* __restrict__ Alo,
              const us* __restrict__ Whi, const us* __restrict__ Wlo,
              float* __restrict__ C, int Mrows, int ldc) {
    extern __shared__ char smc[];
    int bm = blockIdx.x * 128, bn = blockIdx.y * 128;
    float acc[2][8][4];
    gemm_main(smc, Ahi, Alo, Whi, Wlo, bm, bn, Mrows, acc);
    int lane = threadIdx.x & 31, wid = threadIdx.x >> 5;
    int g = lane >> 2, tig = lane & 3;
#pragma unroll
    for (int mt = 0; mt < 2; mt++) {
        int row0 = bm + (wid & 3) * 32 + mt * 16 + g;
#pragma unroll
        for (int nt = 0; nt < 8; nt++) {
            int col = bn + (wid >> 2) * 64 + nt * 8 + tig * 2;
            if (row0 < Mrows)
                *(float2*)(C + (size_t)row0 * ldc + col) =
                    make_float2(acc[mt][nt][0], acc[mt][nt][1]);
            if (row0 + 8 < Mrows)
                *(float2*)(C + (size_t)(row0 + 8) * ldc + col) =
                    make_float2(acc[mt][nt][2], acc[mt][nt][3]);
        }
    }
}

// ---------------- GEMM (sumg @ Wh2^T) with fused GRU update ------------------
__device__ __forceinline__ void gru2(int row, int col, float a0, float a1,
                                     const float* __restrict__ bz,
                                     const float* __restrict__ bh,
                                     float* __restrict__ Hout) {
    if (row >= MM) return;
    size_t e768 = (size_t)g_vid[row] * 768 + col;
    size_t o256 = (size_t)row * 256 + col;
    float2 xz = *(const float2*)(g_emb3 + e768);
    float2 xh = *(const float2*)(g_emb3 + e768 + 512);
    float2 zl = __half22float2(*(const __half2*)(g_zlin + o256));
    us2 shh = *(const us2*)(g_shhi + o256);
    us2 shl = *(const us2*)(g_shlo + o256);
    float2 bzv = *(const float2*)(bz + col);
    float2 bhv = *(const float2*)(bh + col);
    float sh0 = join_bf(shh.x, shl.x);
    float sh1 = join_bf(shh.y, shl.y);
    float z0 = sigmf(xz.x + zl.x + bzv.x);
    float p0 = tanhf(xh.x + a0 + bhv.x);
    float o0 = (1.0f - z0) * sh0 + z0 * p0;
    float z1 = sigmf(xz.y + zl.y + bzv.y);
    float p1 = tanhf(xh.y + a1 + bhv.y);
    float o1 = (1.0f - z1) * sh1 + z1 * p1;
    if (row == 0) { o0 = 0.0f; o1 = 0.0f; }
    *(float2*)(Hout + o256) = make_float2(o0, o1);
    us2 hi, lo;
    split_bf(o0, hi.x, lo.x); split_bf(o1, hi.y, lo.y);
    *(us2*)(g_hhi + o256) = hi;
    *(us2*)(g_hlo + o256) = lo;
}

__global__ __launch_bounds__(256)
void k_gemm_gru(const us* __restrict__ Ahi, const us* __restrict__ Alo,
                const us* __restrict__ Whi, const us* __restrict__ Wlo,
                float* __restrict__ Hout, const float* __restrict__ bz,
                const float* __restrict__ bh) {
    extern __shared__ char smc[];
    int bm = blockIdx.x * 128, bn = blockIdx.y * 128;
    float acc[2][8][4];
    gemm_main(smc, Ahi, Alo, Whi, Wlo, bm, bn, MM, acc);
    int lane = threadIdx.x & 31, wid = threadIdx.x >> 5;
    int g = lane >> 2, tig = lane & 3;
#pragma unroll
    for (int mt = 0; mt < 2; mt++) {
        int row0 = bm + (wid & 3) * 32 + mt * 16 + g;
#pragma unroll
        for (int nt = 0; nt < 8; nt++) {
            int col = bn + (wid >> 2) * 64 + nt * 8 + tig * 2;
            gru2(row0, col, acc[mt][nt][0], acc[mt][nt][1], bz, bh, Hout);
            gru2(row0 + 8, col, acc[mt][nt][2], acc[mt][nt][3], bz, bh, Hout);
        }
    }
}

// ---------------------------------------------------------------------------
// first GRU step (h == 0)
// ---------------------------------------------------------------------------
__global__ void k_first(float* __restrict__ h, const float* __restrict__ bz,
                        const float* __restrict__ bh) {
    int e = blockIdx.x * blockDim.x + threadIdx.x;
    if (e >= MM * 64) return;
    int m = e >> 6, c = (e & 63) * 4;
    size_t e768 = (size_t)g_vid[m] * 768 + c;
    float4 xz = *(const float4*)(g_emb3 + e768);
    float4 xh = *(const float4*)(g_emb3 + e768 + 512);
    float4 bzv = *(const float4*)(bz + c);
    float4 bhv = *(const float4*)(bh + c);
    float4 o;
    o.x = sigmf(xz.x + bzv.x) * tanhf(xh.x + bhv.x);
    o.y = sigmf(xz.y + bzv.y) * tanhf(xh.y + bhv.y);
    o.z = sigmf(xz.z + bzv.z) * tanhf(xh.z + bhv.z);
    o.w = sigmf(xz.w + bzv.w) * tanhf(xh.w + bhv.w);
    if (m == 0) o = make_float4(0.f, 0.f, 0.f, 0.f);
    *(float4*)(h + (size_t)m * HH + c) = o;
    us4 hi, lo;
    split_bf(o.x, hi.x, lo.x); split_bf(o.y, hi.y, lo.y);
    split_bf(o.z, hi.z, lo.z); split_bf(o.w, hi.w, lo.w);
    *(us4*)(g_hhi + (size_t)m * HH + c) = hi;
    *(us4*)(g_hlo + (size_t)m * HH + c) = lo;
}

// ---------------------------------------------------------------------------
// gather
// ---------------------------------------------------------------------------
__global__ void k_gather(const float* __restrict__ h, const int* __restrict__ mg,
                         const float* __restrict__ bu) {
    int m = blockIdx.x * blockDim.y + threadIdx.y;
    if (m >= MM) return;
    int c = threadIdx.x * 4;
    int idx[KK];
#pragma unroll
    for (int k = 0; k < KK; k++) idx[k] = mg[m * KK + k];
    float4 xr = *(const float4*)(g_emb3 + (size_t)g_vid[m] * 768 + 256 + c);
    float4 bv = *(const float4*)(bu + c);
    float4 as = make_float4(0.f, 0.f, 0.f, 0.f);
    float4 ag = make_float4(0.f, 0.f, 0.f, 0.f);
#pragma unroll
    for (int k = 0; k < KK; k++) {
        const float4 hv = *(const float4*)(h + (size_t)idx[k] * HH + c);
        const __half2* up = (const __half2*)(g_hUr + (size_t)idx[k] * HH + c);
        float2 u0 = __half22float2(up[0]);
        float2 u1 = __half22float2(up[1]);
        float rx = sigmf(xr.x + u0.x + bv.x);
        float ry = sigmf(xr.y + u0.y + bv.y);
        float rz = sigmf(xr.z + u1.x + bv.z);
        float rw = sigmf(xr.w + u1.y + bv.w);
        as.x += hv.x; as.y += hv.y; as.z += hv.z; as.w += hv.w;
        ag.x = fmaf(rx, hv.x, ag.x); ag.y = fmaf(ry, hv.y, ag.y);
        ag.z = fmaf(rz, hv.z, ag.z); ag.w = fmaf(rw, hv.w, ag.w);
    }
    us4 hi, lo;
    split_bf(as.x, hi.x, lo.x); split_bf(as.y, hi.y, lo.y);
    split_bf(as.z, hi.z, lo.z); split_bf(as.w, hi.w, lo.w);
    *(us4*)(g_shhi + (size_t)m * HH + c) = hi;
    *(us4*)(g_shlo + (size_t)m * HH + c) = lo;
    split_bf(ag.x, hi.x, lo.x); split_bf(ag.y, hi.y, lo.y);
    split_bf(ag.z, hi.z, lo.z); split_bf(ag.w, hi.w, lo.w);
    *(us4*)(g_sghi + (size_t)m * HH + c) = hi;
    *(us4*)(g_sglo + (size_t)m * HH + c) = lo;
}

// ---------------------------------------------------------------------------
// readout (B=64 roots)
// ---------------------------------------------------------------------------
__global__ void k_readout(const int* __restrict__ scope_st, const int* __restrict__ fnode,
                          const int* __restrict__ node_graph, const float* __restrict__ emb,
                          const float* __restrict__ h, const float* __restrict__ Wo,
                          const float* __restrict__ bo, float* __restrict__ out) {
    __shared__ float fe[HH];
    __shared__ float mn[HH];
    int b = blockIdx.x, j = threadIdx.x;
    int n = scope_st[b];
    fe[j] = emb[(size_t)fnode[n] * HH + j];
    float s = 0.0f;
#pragma unroll
    for (int k = 0; k < KK; k++) s += h[(size_t)node_graph[n * KK + k] * HH + j];
    mn[j] = s;
    __syncthreads();
    float acc = bo[j];
    const float* wrow = Wo + (size_t)j * 512;
#pragma unroll 4
    for (int i = 0; i < 256; i += 4) {
        float4 w = *(const float4*)(wrow + i);
        float4 f = *(const float4*)&fe[i];
        acc = fmaf(w.x, f.x, acc); acc = fmaf(w.y, f.y, acc);
        acc = fmaf(w.z, f.z, acc); acc = fmaf(w.w, f.w, acc);
    }
#pragma unroll 4
    for (int i = 0; i < 256; i += 4) {
        float4 w = *(const float4*)(wrow + 256 + i);
        float4 f = *(const float4*)&mn[i];
        acc = fmaf(w.x, f.x, acc); acc = fmaf(w.y, f.y, acc);
        acc = fmaf(w.z, f.z, acc); acc = fmaf(w.w, f.w, acc);
    }
    out[(size_t)b * HH + j] = fmaxf(acc, 0.0f);
}

// ---------------------------------------------------------------------------
// launch
// ---------------------------------------------------------------------------
extern "C" void kernel_launch(void* const* d_in, const int* in_sizes, int n_in,
                              void* d_out, int out_size) {
    const int*   fnode      = (const int*)  d_in[0];
    const int*   fmess      = (const int*)  d_in[1];
    const int*   node_graph = (const int*)  d_in[2];
    const int*   mess_graph = (const int*)  d_in[3];
    const int*   scope_st   = (const int*)  d_in[4];
    const float* emb        = (const float*)d_in[5];
    const float* Wz         = (const float*)d_in[6];
    const float* bz         = (const float*)d_in[7];
    const float* Wr         = (const float*)d_in[8];
    const float* Ur         = (const float*)d_in[9];
    const float* bu         = (const float*)d_in[10];
    const float* Wh         = (const float*)d_in[11];
    const float* bh         = (const float*)d_in[12];
    const float* Wo         = (const float*)d_in[13];
    const float* bo         = (const float*)d_in[14];

    float* out = (float*)d_out;
    float* h = out + (size_t)BB * HH;

    cudaFuncSetAttribute(k_gemm_f,   cudaFuncAttributeMaxDynamicSharedMemorySize, SMEM_GEMM);
    cudaFuncSetAttribute(k_gemm_gru, cudaFuncAttributeMaxDynamicSharedMemorySize, SMEM_GEMM);
    cudaFuncSetAttribute(k_gemm1_h,  cudaFuncAttributeMaxDynamicSharedMemorySize, SMEM_GEMM1);

    us *hhi, *hlo, *shhi, *shlo, *sghi, *sglo, *embhi, *emblo;
    us *Wprehi, *Wprelo, *Wz2hi, *Wz2lo, *Wh2hi, *Wh2lo, *Urhi, *Urlo;
    __half *hUrp, *zlinp; float *emb3p;
    cudaGetSymbolAddress((void**)&hhi, g_hhi);   cudaGetSymbolAddress((void**)&hlo, g_hlo);
    cudaGetSymbolAddress((void**)&shhi, g_shhi); cudaGetSymbolAddress((void**)&shlo, g_shlo);
    cudaGetSymbolAddress((void**)&sghi, g_sghi); cudaGetSymbolAddress((void**)&sglo, g_sglo);
    cudaGetSymbolAddress((void**)&embhi, g_embhi); cudaGetSymbolAddress((void**)&emblo, g_emblo);
    cudaGetSymbolAddress((void**)&Wprehi, g_Wprehi); cudaGetSymbolAddress((void**)&Wprelo, g_Wprelo);
    cudaGetSymbolAddress((void**)&Wz2hi, g_Wz2hi);   cudaGetSymbolAddress((void**)&Wz2lo, g_Wz2lo);
    cudaGetSymbolAddress((void**)&Wh2hi, g_Wh2hi);   cudaGetSymbolAddress((void**)&Wh2lo, g_Wh2lo);
    cudaGetSymbolAddress((void**)&Urhi, g_Urhi);     cudaGetSymbolAddress((void**)&Urlo, g_Urlo);
    cudaGetSymbolAddress((void**)&emb3p, g_emb3);
    cudaGetSymbolAddress((void**)&zlinp, g_zlin);
    cudaGetSymbolAddress((void**)&hUrp, g_hUr);

    const int ETH = 256;
    const int EBL = (MM * 64 + ETH - 1) / ETH;
    const int MT  = (MM + 127) / 128;
    const int VT  = (VV + 127) / 128;

    k_pack   <<<1536, 256>>>(Wz, Wr, Wh, Ur);
    k_packemb<<<(VV * 256 + 255) / 256, 256>>>(emb);
    k_vid    <<<(MM + 255) / 256, 256>>>(fnode, fmess);

    k_gemm_f<<<dim3(VT, 6), 256, SMEM_GEMM>>>(embhi, emblo, Wprehi, Wprelo, emb3p, VV, 768);
    k_first<<<EBL, ETH>>>(h, bz, bh);

    for (int it = 1; it < NDEPTH; it++) {
        k_gemm1_h<<<dim3(MT, 2), 256, SMEM_GEMM1>>>(hhi, Urhi, hUrp, 256);    // r-gate: 1-term
        k_gather<<<(MM + 3) / 4, dim3(64, 4)>>>(h, mess_graph, bu);
        k_gemm1_h<<<dim3(MT, 2), 256, SMEM_GEMM1>>>(shhi, Wz2hi, zlinp, 256); // z-gate: 1-term
        k_gemm_gru<<<dim3(MT, 2), 256, SMEM_GEMM>>>(sghi, sglo, Wh2hi, Wh2lo, h, bz, bh);
    }

    k_readout<<<BB, HH>>>(scope_st, fnode, node_graph, emb, h, Wo, bo, out);
}